// round 5
// baseline (speedup 1.0000x reference)
#include <cuda_runtime.h>
#include <cstdint>

#define NB   2
#define NT   2048
#define ND   2048
#define NHQ  32
#define NHKV 8
#define NDH  64
#define NTOK (NB*NT)      // 4096
#define NDKV (NHKV*NDH)   // 512

// scratch (device globals: allocation-free per harness rules)
__device__ float g_Q[(size_t)NTOK * ND];    // 32 MB
__device__ float g_K[(size_t)NTOK * NDKV];  // 8 MB
__device__ float g_V[(size_t)NTOK * NDKV];  // 8 MB
__device__ float g_A[(size_t)NTOK * ND];    // 32 MB

// ---------------------------------------------------------------------------
// tf32 helpers
// ---------------------------------------------------------------------------
__device__ __forceinline__ float to_tf32(float x) {
    float r;
    asm("cvt.rna.tf32.f32 %0, %1;" : "=f"(r) : "f"(x));
    return r;
}

__device__ __forceinline__ void mma_tf32(float* c, uint32_t a0, uint32_t a1,
                                         uint32_t a2, uint32_t a3,
                                         uint32_t b0, uint32_t b1) {
    asm volatile(
        "mma.sync.aligned.m16n8k8.row.col.f32.tf32.tf32.f32 "
        "{%0,%1,%2,%3}, {%4,%5,%6,%7}, {%8,%9}, {%0,%1,%2,%3};"
        : "+f"(c[0]), "+f"(c[1]), "+f"(c[2]), "+f"(c[3])
        : "r"(a0), "r"(a1), "r"(a2), "r"(a3), "r"(b0), "r"(b1));
}

__device__ __forceinline__ void cp_async16(void* smem_ptr, const void* gptr) {
    unsigned saddr = (unsigned)__cvta_generic_to_shared(smem_ptr);
    asm volatile("cp.async.cg.shared.global [%0], [%1], 16;\n"
                 :: "r"(saddr), "l"(gptr));
}

// ---------------------------------------------------------------------------
// tf32 tensor-core GEMM core with register-prefetch double buffering.
// C[M,N] = A[M,K] @ B[K,N], row-major fp32. 128x128 tile, BK=16, 256 thr.
// ---------------------------------------------------------------------------
__device__ __forceinline__ void gemm_core(
    const float* __restrict__ A, const float* __restrict__ B,
    float* __restrict__ C, int N, int K, int bx, int by)
{
    __shared__ float As[16][136];   // [k][m]
    __shared__ float Bs[16][136];   // [k][n]

    const int tid  = threadIdx.x;
    const int warp = tid >> 5;
    const int lane = tid & 31;
    const int g    = lane >> 2;
    const int t    = lane & 3;
    const int mbase = (warp >> 2) * 64;
    const int nbase = (warp & 3) * 32;

    const int ar = tid >> 1;
    const int ac = (tid & 1) * 8;
    const int br = tid >> 4;
    const int bc = (tid & 15) * 8;

    const float* Ab = A + (size_t)(by * 128 + ar) * K + ac;
    const float* Bb = B + (size_t)br * N + bx * 128 + bc;

    float acc[4][4][4];
    #pragma unroll
    for (int i = 0; i < 4; i++)
        #pragma unroll
        for (int j = 0; j < 4; j++)
            #pragma unroll
            for (int r = 0; r < 4; r++) acc[i][j][r] = 0.f;

    // stage tile 0 into registers
    float4 a0 = *(const float4*)(Ab);
    float4 a1 = *(const float4*)(Ab + 4);
    float4 b0 = *(const float4*)(Bb);
    float4 b1 = *(const float4*)(Bb + 4);

    for (int k0 = 0;;) {
        // STS staged registers (tf32-rounded)
        As[ac + 0][ar] = to_tf32(a0.x);
        As[ac + 1][ar] = to_tf32(a0.y);
        As[ac + 2][ar] = to_tf32(a0.z);
        As[ac + 3][ar] = to_tf32(a0.w);
        As[ac + 4][ar] = to_tf32(a1.x);
        As[ac + 5][ar] = to_tf32(a1.y);
        As[ac + 6][ar] = to_tf32(a1.z);
        As[ac + 7][ar] = to_tf32(a1.w);
        {
            float* d = &Bs[br][bc];
            d[0] = to_tf32(b0.x); d[1] = to_tf32(b0.y);
            d[2] = to_tf32(b0.z); d[3] = to_tf32(b0.w);
            d[4] = to_tf32(b1.x); d[5] = to_tf32(b1.y);
            d[6] = to_tf32(b1.z); d[7] = to_tf32(b1.w);
        }
        __syncthreads();

        const bool nxt = (k0 + 16) < K;
        if (nxt) {   // prefetch next tile into registers (hides L2 latency)
            a0 = *(const float4*)(Ab + k0 + 16);
            a1 = *(const float4*)(Ab + k0 + 20);
            const float* bp = Bb + (size_t)(k0 + 16) * N;
            b0 = *(const float4*)(bp);
            b1 = *(const float4*)(bp + 4);
        }

        #pragma unroll
        for (int ks = 0; ks < 16; ks += 8) {
            uint32_t af[4][4];
            #pragma unroll
            for (int mf = 0; mf < 4; mf++) {
                const int m0 = mbase + mf * 16 + g;
                af[mf][0] = __float_as_uint(As[ks + t    ][m0]);
                af[mf][1] = __float_as_uint(As[ks + t    ][m0 + 8]);
                af[mf][2] = __float_as_uint(As[ks + t + 4][m0]);
                af[mf][3] = __float_as_uint(As[ks + t + 4][m0 + 8]);
            }
            uint32_t bf[4][2];
            #pragma unroll
            for (int nf = 0; nf < 4; nf++) {
                const int n0 = nbase + nf * 8 + g;
                bf[nf][0] = __float_as_uint(Bs[ks + t    ][n0]);
                bf[nf][1] = __float_as_uint(Bs[ks + t + 4][n0]);
            }
            #pragma unroll
            for (int mf = 0; mf < 4; mf++)
                #pragma unroll
                for (int nf = 0; nf < 4; nf++)
                    mma_tf32(acc[mf][nf], af[mf][0], af[mf][1], af[mf][2],
                             af[mf][3], bf[nf][0], bf[nf][1]);
        }
        if (!nxt) break;
        k0 += 16;
        __syncthreads();
    }

    #pragma unroll
    for (int mf = 0; mf < 4; mf++) {
        const int row = by * 128 + mbase + mf * 16 + g;
        #pragma unroll
        for (int nf = 0; nf < 4; nf++) {
            const int col = bx * 128 + nbase + nf * 8 + 2 * t;
            *(float2*)(C + (size_t)row * N + col) =
                make_float2(acc[mf][nf][0], acc[mf][nf][1]);
            *(float2*)(C + (size_t)(row + 8) * N + col) =
                make_float2(acc[mf][nf][2], acc[mf][nf][3]);
        }
    }
}

// fused Q/K/V projection: grid (24, 32); bx<16 -> Q, <20 -> K, else -> V
__global__ __launch_bounds__(256) void gemm_qkv(
    const float* __restrict__ x,
    const float* __restrict__ Wq, const float* __restrict__ Wk,
    const float* __restrict__ Wv,
    float* __restrict__ Qp, float* __restrict__ Kp, float* __restrict__ Vp)
{
    const int bx = blockIdx.x;
    if (bx < 16)      gemm_core(x, Wq, Qp, ND,   ND, bx,      blockIdx.y);
    else if (bx < 20) gemm_core(x, Wk, Kp, NDKV, ND, bx - 16, blockIdx.y);
    else              gemm_core(x, Wv, Vp, NDKV, ND, bx - 20, blockIdx.y);
}

__global__ __launch_bounds__(256) void gemm_out(
    const float* __restrict__ A, const float* __restrict__ B,
    float* __restrict__ C)
{
    gemm_core(A, B, C, ND, ND, blockIdx.x, blockIdx.y);
}

// ---------------------------------------------------------------------------
// MMA flash attention (tf32), software-pipelined:
//   per iter: softmax(kb) | barrier | STS V(kb+1), prefetch(kb+2), QK(kb+1) | PV(kb)
// Br=128 (8 warps x 16 rows), Bc=64, dh=64. Q in registers; softmax in
// registers (exp2 domain); K double-buffered cp.async; V via LDG+transposed STS.
// ---------------------------------------------------------------------------
#define FA_P 68
#define FA2_SMEM (4 * 64 * FA_P * (int)sizeof(float))   // 69632 B

__global__ __launch_bounds__(256) void flash_mma(
    const float* __restrict__ Q, const float* __restrict__ K,
    const float* __restrict__ V, float* __restrict__ O)
{
    extern __shared__ float sm[];
    float* sKb[2]  = { sm,                sm + 2 * 64 * FA_P };
    float* sVt[2]  = { sm + 64 * FA_P,    sm + 3 * 64 * FA_P };
    float* Qs      = sm + 2 * 64 * FA_P;  // 128 x 68, aliases buffers 2+3

    const int tid  = threadIdx.x;
    const int warp = tid >> 5;
    const int lane = tid & 31;
    const int g    = lane >> 2;      // 0..7
    const int tq   = lane & 3;       // 0..3
    const int bh   = blockIdx.y;
    const int b    = bh >> 5;
    const int h    = bh & 31;
    const int hkv  = h >> 2;
    const int q0   = blockIdx.x * 128;

    const int krow = tid >> 2;          // 0..63
    const int kcol = (tid & 3) * 16;    // 0,16,32,48
    const int vrow = tid & 63;
    const int vcb  = (tid >> 6) * 16;

    // --- prologue: cp.async K tile 0 ---
    {
        const float* src = K + (size_t)(b * NT + krow) * NDKV + hkv * NDH + kcol;
        #pragma unroll
        for (int i = 0; i < 4; i++)
            cp_async16(&sKb[0][krow * FA_P + kcol + 4 * i], src + 4 * i);
        asm volatile("cp.async.commit_group;\n" ::: "memory");
    }
    // --- V tile 0: LDG into registers ---
    float4 vr[4];
    {
        const float* src = V + (size_t)(b * NT + vrow) * NDKV + hkv * NDH + vcb;
        #pragma unroll
        for (int i = 0; i < 4; i++) vr[i] = *(const float4*)(src + 4 * i);
    }
    // --- stage Q (scale folded with log2e for exp2 softmax), tf32-rounded ---
    const float QSC = 0.18033688011112042f;   // 0.125 * log2(e)
    {
        const int r  = tid >> 1;
        const int c0 = (tid & 1) * 32;
        const float* src = Q + (size_t)(b * NT + q0 + r) * ND + h * NDH + c0;
        #pragma unroll
        for (int i = 0; i < 8; i++) {
            float4 v = *(const float4*)(src + 4 * i);
            float* d = &Qs[r * FA_P + c0 + 4 * i];
            d[0] = to_tf32(QSC * v.x);
            d[1] = to_tf32(QSC * v.y);
            d[2] = to_tf32(QSC * v.z);
            d[3] = to_tf32(QSC * v.w);
        }
    }
    __syncthreads();

    // --- Q fragments into registers (held for entire KV loop) ---
    uint32_t qa[8][4];
    {
        const float* qr0 = &Qs[(warp * 16 + g) * FA_P];
        const float* qr1 = qr0 + 8 * FA_P;
        #pragma unroll
        for (int ks = 0; ks < 8; ks++) {
            qa[ks][0] = __float_as_uint(qr0[8 * ks + tq]);
            qa[ks][1] = __float_as_uint(qr1[8 * ks + tq]);
            qa[ks][2] = __float_as_uint(qr0[8 * ks + tq + 4]);
            qa[ks][3] = __float_as_uint(qr1[8 * ks + tq + 4]);
        }
    }
    // --- STS V tile 0 (transposed, rounded) ---
    {
        float* dst = sVt[0];
        #pragma unroll
        for (int i = 0; i < 4; i++) {
            dst[(vcb + 4 * i + 0) * FA_P + vrow] = to_tf32(vr[i].x);
            dst[(vcb + 4 * i + 1) * FA_P + vrow] = to_tf32(vr[i].y);
            dst[(vcb + 4 * i + 2) * FA_P + vrow] = to_tf32(vr[i].z);
            dst[(vcb + 4 * i + 3) * FA_P + vrow] = to_tf32(vr[i].w);
        }
    }
    __syncthreads();   // all Qs reads done (Qs aliases sKb[1]); sVt[0] ready

    // --- issue K tile 1 + LDG V tile 1 ---
    {
        const float* src = K + (size_t)(b * NT + 64 + krow) * NDKV + hkv * NDH + kcol;
        #pragma unroll
        for (int i = 0; i < 4; i++)
            cp_async16(&sKb[1][krow * FA_P + kcol + 4 * i], src + 4 * i);
        asm volatile("cp.async.commit_group;\n" ::: "memory");
    }
    {
        const float* src = V + (size_t)(b * NT + 64 + vrow) * NDKV + hkv * NDH + vcb;
        #pragma unroll
        for (int i = 0; i < 4; i++) vr[i] = *(const float4*)(src + 4 * i);
    }
    asm volatile("cp.async.wait_group 1;\n" ::: "memory");   // K0 done
    __syncthreads();

    // --- QK(0) -> s ---
    float s[8][4];
    #pragma unroll
    for (int j = 0; j < 8; j++)
        #pragma unroll
        for (int r = 0; r < 4; r++) s[j][r] = 0.f;
    {
        const float* kp = sKb[0];
        #pragma unroll
        for (int ks = 0; ks < 8; ks++)
            #pragma unroll
            for (int j = 0; j < 8; j++) {
                const float b0 = kp[(8 * j + g) * FA_P + 8 * ks + tq];
                const float b1 = kp[(8 * j + g) * FA_P + 8 * ks + tq + 4];
                mma_tf32(s[j], qa[ks][0], qa[ks][1], qa[ks][2], qa[ks][3],
                         __float_as_uint(b0), __float_as_uint(b1));
            }
    }

    float m0 = -1e30f, m1 = -1e30f, l0 = 0.f, l1 = 0.f;
    float acc_o[8][4];
    #pragma unroll
    for (int j = 0; j < 8; j++)
        #pragma unroll
        for (int r = 0; r < 4; r++) acc_o[j][r] = 0.f;

    const unsigned fm   = 0xffffffffu;
    const int      src0 = (lane & 28) | (tq >> 1);
    const int      src2 = src0 + 2;

    for (int kb = 0; kb < NT / 64; kb++) {
        const int cb = kb & 1;
        const bool pre1 = kb + 1 < NT / 64;
        const bool pre2 = kb + 2 < NT / 64;

        // --- online softmax on s (exp2 domain); overlaps prev PV MMA latency ---
        float mt0 = -1e30f, mt1 = -1e30f;
        #pragma unroll
        for (int j = 0; j < 8; j++) {
            mt0 = fmaxf(mt0, fmaxf(s[j][0], s[j][1]));
            mt1 = fmaxf(mt1, fmaxf(s[j][2], s[j][3]));
        }
        mt0 = fmaxf(mt0, __shfl_xor_sync(fm, mt0, 1));
        mt0 = fmaxf(mt0, __shfl_xor_sync(fm, mt0, 2));
        mt1 = fmaxf(mt1, __shfl_xor_sync(fm, mt1, 1));
        mt1 = fmaxf(mt1, __shfl_xor_sync(fm, mt1, 2));
        const float mn0 = fmaxf(m0, mt0);
        const float mn1 = fmaxf(m1, mt1);
        const float al0 = exp2f(m0 - mn0);
        const float al1 = exp2f(m1 - mn1);
        m0 = mn0; m1 = mn1;
        float rs0 = 0.f, rs1 = 0.f;
        #pragma unroll
        for (int j = 0; j < 8; j++) {
            s[j][0] = exp2f(s[j][0] - mn0); rs0 += s[j][0];
            s[j][1] = exp2f(s[j][1] - mn0); rs0 += s[j][1];
            s[j][2] = exp2f(s[j][2] - mn1); rs1 += s[j][2];
            s[j][3] = exp2f(s[j][3] - mn1); rs1 += s[j][3];
        }
        rs0 += __shfl_xor_sync(fm, rs0, 1);
        rs0 += __shfl_xor_sync(fm, rs0, 2);
        rs1 += __shfl_xor_sync(fm, rs1, 1);
        rs1 += __shfl_xor_sync(fm, rs1, 2);
        l0 = l0 * al0 + rs0;
        l1 = l1 * al1 + rs1;
        #pragma unroll
        for (int j = 0; j < 8; j++) {
            acc_o[j][0] *= al0; acc_o[j][1] *= al0;
            acc_o[j][2] *= al1; acc_o[j][3] *= al1;
        }

        if (pre1) asm volatile("cp.async.wait_group 0;\n" ::: "memory");
        __syncthreads();   // K(kb+1) visible; all warps done with QK(kb)/PV(kb-1)

        // --- STS V(kb+1) (transposed, rounded) ---
        if (pre1) {
            float* dst = sVt[cb ^ 1];
            #pragma unroll
            for (int i = 0; i < 4; i++) {
                dst[(vcb + 4 * i + 0) * FA_P + vrow] = to_tf32(vr[i].x);
                dst[(vcb + 4 * i + 1) * FA_P + vrow] = to_tf32(vr[i].y);
                dst[(vcb + 4 * i + 2) * FA_P + vrow] = to_tf32(vr[i].z);
                dst[(vcb + 4 * i + 3) * FA_P + vrow] = to_tf32(vr[i].w);
            }
        }
        // --- prefetch tile kb+2 ---
        if (pre2) {
            const float* src = K + (size_t)(b * NT + (kb + 2) * 64 + krow) * NDKV
                               + hkv * NDH + kcol;
            #pragma unroll
            for (int i = 0; i < 4; i++)
                cp_async16(&sKb[cb][krow * FA_P + kcol + 4 * i], src + 4 * i);
            asm volatile("cp.async.commit_group;\n" ::: "memory");
            const float* vsrc = V + (size_t)(b * NT + (kb + 2) * 64 + vrow) * NDKV
                                + hkv * NDH + vcb;
            #pragma unroll
            for (int i = 0; i < 4; i++) vr[i] = *(const float4*)(vsrc + 4 * i);
        }

        // --- QK(kb+1) -> s2 (independent of softmax output: fills tensor pipe) ---
        float s2[8][4];
        if (pre1) {
            #pragma unroll
            for (int j = 0; j < 8; j++)
                #pragma unroll
                for (int r = 0; r < 4; r++) s2[j][r] = 0.f;
            const float* kp = sKb[cb ^ 1];
            #pragma unroll
            for (int ks = 0; ks < 8; ks++)
                #pragma unroll
                for (int j = 0; j < 8; j++) {
                    const float b0 = kp[(8 * j + g) * FA_P + 8 * ks + tq];
                    const float b1 = kp[(8 * j + g) * FA_P + 8 * ks + tq + 4];
                    mma_tf32(s2[j], qa[ks][0], qa[ks][1], qa[ks][2], qa[ks][3],
                             __float_as_uint(b0), __float_as_uint(b1));
                }
        }

        // --- PV(kb): C-layout -> A-layout via quad shuffles, then MMA ---
        {
            const float* vt = sVt[cb];
            const bool odd = tq & 1;
            #pragma unroll
            for (int ks = 0; ks < 8; ks++) {
                const float e00 = __shfl_sync(fm, s[ks][0], src0);
                const float e01 = __shfl_sync(fm, s[ks][1], src0);
                const float e10 = __shfl_sync(fm, s[ks][2], src0);
                const float e11 = __shfl_sync(fm, s[ks][3], src0);
                const float e20 = __shfl_sync(fm, s[ks][0], src2);
                const float e21 = __shfl_sync(fm, s[ks][1], src2);
                const float e30 = __shfl_sync(fm, s[ks][2], src2);
                const float e31 = __shfl_sync(fm, s[ks][3], src2);
                const uint32_t pa0 = __float_as_uint(to_tf32(odd ? e01 : e00));
                const uint32_t pa1 = __float_as_uint(to_tf32(odd ? e11 : e10));
                const uint32_t pa2 = __float_as_uint(to_tf32(odd ? e21 : e20));
                const uint32_t pa3 = __float_as_uint(to_tf32(odd ? e31 : e30));
                #pragma unroll
                for (int jd = 0; jd < 8; jd++) {
                    const float b0 = vt[(8 * jd + g) * FA_P + 8 * ks + tq];
                    const float b1 = vt[(8 * jd + g) * FA_P + 8 * ks + tq + 4];
                    mma_tf32(acc_o[jd], pa0, pa1, pa2, pa3,
                             __float_as_uint(b0), __float_as_uint(b1));
                }
            }
        }

        if (pre1) {
            #pragma unroll
            for (int j = 0; j < 8; j++)
                #pragma unroll
                for (int r = 0; r < 4; r++) s[j][r] = s2[j][r];
        }
    }

    // --- epilogue: normalize and store ---
    const float inv0 = 1.0f / l0;
    const float inv1 = 1.0f / l1;
    const size_t row0 = (size_t)(b * NT + q0 + warp * 16 + g);
    float* o0 = O + row0 * ND + h * NDH;
    float* o1 = o0 + (size_t)8 * ND;
    #pragma unroll
    for (int jd = 0; jd < 8; jd++) {
        *(float2*)(o0 + 8 * jd + 2 * tq) =
            make_float2(acc_o[jd][0] * inv0, acc_o[jd][1] * inv0);
        *(float2*)(o1 + 8 * jd + 2 * tq) =
            make_float2(acc_o[jd][2] * inv1, acc_o[jd][3] * inv1);
    }
}

// ---------------------------------------------------------------------------
extern "C" void kernel_launch(void* const* d_in, const int* in_sizes, int n_in,
                              void* d_out, int out_size)
{
    const float* x  = (const float*)d_in[0];
    const float* Wq = (const float*)d_in[1];
    const float* Wk = (const float*)d_in[2];
    const float* Wv = (const float*)d_in[3];
    const float* Wo = (const float*)d_in[4];
    float* out = (float*)d_out;

    float *Qp, *Kp, *Vp, *Ap;
    cudaGetSymbolAddress((void**)&Qp, g_Q);
    cudaGetSymbolAddress((void**)&Kp, g_K);
    cudaGetSymbolAddress((void**)&Vp, g_V);
    cudaGetSymbolAddress((void**)&Ap, g_A);

    cudaFuncSetAttribute(flash_mma,
                         cudaFuncAttributeMaxDynamicSharedMemorySize, FA2_SMEM);

    gemm_qkv<<<dim3(24, 32), 256>>>(x, Wq, Wk, Wv, Qp, Kp, Vp);
    flash_mma<<<dim3(NT / 128, NB * NHQ), 256, FA2_SMEM>>>(Qp, Kp, Vp, Ap);
    gemm_out<<<dim3(16, 32), 256>>>(Ap, Wo, out);
}

// round 6
// speedup vs baseline: 1.0930x; 1.0930x over previous
#include <cuda_runtime.h>
#include <cstdint>

#define NB   2
#define NT   2048
#define ND   2048
#define NHQ  32
#define NHKV 8
#define NDH  64
#define NTOK (NB*NT)      // 4096
#define NDKV (NHKV*NDH)   // 512

// scratch (device globals: allocation-free per harness rules)
__device__ float g_Q[(size_t)NTOK * ND];    // 32 MB
__device__ float g_K[(size_t)NTOK * NDKV];  // 8 MB
__device__ float g_V[(size_t)NTOK * NDKV];  // 8 MB
__device__ float g_A[(size_t)NTOK * ND];    // 32 MB

// ---------------------------------------------------------------------------
// tf32 helpers
// ---------------------------------------------------------------------------
__device__ __forceinline__ float to_tf32(float x) {
    float r;
    asm("cvt.rna.tf32.f32 %0, %1;" : "=f"(r) : "f"(x));
    return r;
}

__device__ __forceinline__ void mma_tf32(float* c, uint32_t a0, uint32_t a1,
                                         uint32_t a2, uint32_t a3,
                                         uint32_t b0, uint32_t b1) {
    asm volatile(
        "mma.sync.aligned.m16n8k8.row.col.f32.tf32.tf32.f32 "
        "{%0,%1,%2,%3}, {%4,%5,%6,%7}, {%8,%9}, {%0,%1,%2,%3};"
        : "+f"(c[0]), "+f"(c[1]), "+f"(c[2]), "+f"(c[3])
        : "r"(a0), "r"(a1), "r"(a2), "r"(a3), "r"(b0), "r"(b1));
}

__device__ __forceinline__ void cp_async16(void* smem_ptr, const void* gptr) {
    unsigned saddr = (unsigned)__cvta_generic_to_shared(smem_ptr);
    asm volatile("cp.async.cg.shared.global [%0], [%1], 16;\n"
                 :: "r"(saddr), "l"(gptr));
}

// ---------------------------------------------------------------------------
// tf32 GEMM: block 256x128, BK=16, 256 threads = 8 warps (4x2), warp 64x64.
// Every B-fragment feeds 4 m-frags worth? no: each af/bf pair reused across
// the 4x8 frag grid -> 32 LDS-32 per thread per k8 for 32 MMAs (16 FLOP/B).
// C[M,N] = A[M,K] @ B[K,N], row-major fp32. M%256==0, N%128==0, K%16==0.
// ---------------------------------------------------------------------------
__device__ __forceinline__ void gemm_core(
    const float* __restrict__ A, const float* __restrict__ B,
    float* __restrict__ C, int N, int K, int bx, int by)
{
    __shared__ float As[16][264];   // [k][m], pitch 264 (mod32=8): reads conflict-free
    __shared__ float Bs[16][136];   // [k][n]

    const int tid  = threadIdx.x;
    const int warp = tid >> 5;
    const int lane = tid & 31;
    const int g    = lane >> 2;
    const int t    = lane & 3;
    const int mbase = (warp >> 1) * 64;   // 0,64,128,192
    const int nbase = (warp & 1) * 64;    // 0,64

    const int br = tid >> 4;              // 0..15
    const int bc = (tid & 15) * 8;        // 0..120

    const float* Ab = A + (size_t)(by * 256 + tid) * K;   // one row per thread
    const float* Bb = B + (size_t)br * N + bx * 128 + bc;

    float acc[4][8][4];
    #pragma unroll
    for (int i = 0; i < 4; i++)
        #pragma unroll
        for (int j = 0; j < 8; j++)
            #pragma unroll
            for (int r = 0; r < 4; r++) acc[i][j][r] = 0.f;

    // stage tile 0 into registers
    float4 a[4], b[2];
    #pragma unroll
    for (int i = 0; i < 4; i++) a[i] = *(const float4*)(Ab + 4 * i);
    b[0] = *(const float4*)(Bb);
    b[1] = *(const float4*)(Bb + 4);

    for (int k0 = 0;;) {
        // STS staged registers (tf32-rounded). A transposed.
        #pragma unroll
        for (int i = 0; i < 4; i++) {
            As[4 * i + 0][tid] = to_tf32(a[i].x);
            As[4 * i + 1][tid] = to_tf32(a[i].y);
            As[4 * i + 2][tid] = to_tf32(a[i].z);
            As[4 * i + 3][tid] = to_tf32(a[i].w);
        }
        {
            float* d = &Bs[br][bc];
            d[0] = to_tf32(b[0].x); d[1] = to_tf32(b[0].y);
            d[2] = to_tf32(b[0].z); d[3] = to_tf32(b[0].w);
            d[4] = to_tf32(b[1].x); d[5] = to_tf32(b[1].y);
            d[6] = to_tf32(b[1].z); d[7] = to_tf32(b[1].w);
        }
        __syncthreads();

        const bool nxt = (k0 + 16) < K;
        if (nxt) {   // prefetch next tile into registers
            #pragma unroll
            for (int i = 0; i < 4; i++)
                a[i] = *(const float4*)(Ab + k0 + 16 + 4 * i);
            const float* bp = Bb + (size_t)(k0 + 16) * N;
            b[0] = *(const float4*)(bp);
            b[1] = *(const float4*)(bp + 4);
        }

        #pragma unroll
        for (int ks = 0; ks < 16; ks += 8) {
            uint32_t af[4][4];
            #pragma unroll
            for (int mf = 0; mf < 4; mf++) {
                const int m0 = mbase + mf * 16 + g;
                af[mf][0] = __float_as_uint(As[ks + t    ][m0]);
                af[mf][1] = __float_as_uint(As[ks + t    ][m0 + 8]);
                af[mf][2] = __float_as_uint(As[ks + t + 4][m0]);
                af[mf][3] = __float_as_uint(As[ks + t + 4][m0 + 8]);
            }
            uint32_t bf[8][2];
            #pragma unroll
            for (int nf = 0; nf < 8; nf++) {
                const int n0 = nbase + nf * 8 + g;
                bf[nf][0] = __float_as_uint(Bs[ks + t    ][n0]);
                bf[nf][1] = __float_as_uint(Bs[ks + t + 4][n0]);
            }
            #pragma unroll
            for (int mf = 0; mf < 4; mf++)
                #pragma unroll
                for (int nf = 0; nf < 8; nf++)
                    mma_tf32(acc[mf][nf], af[mf][0], af[mf][1], af[mf][2],
                             af[mf][3], bf[nf][0], bf[nf][1]);
        }
        if (!nxt) break;
        k0 += 16;
        __syncthreads();
    }

    #pragma unroll
    for (int mf = 0; mf < 4; mf++) {
        const int row = by * 256 + mbase + mf * 16 + g;
        #pragma unroll
        for (int nf = 0; nf < 8; nf++) {
            const int col = bx * 128 + nbase + nf * 8 + 2 * t;
            *(float2*)(C + (size_t)row * N + col) =
                make_float2(acc[mf][nf][0], acc[mf][nf][1]);
            *(float2*)(C + (size_t)(row + 8) * N + col) =
                make_float2(acc[mf][nf][2], acc[mf][nf][3]);
        }
    }
}

// fused Q/K/V projection: grid (24, 16); bx<16 -> Q, <20 -> K, else -> V
__global__ __launch_bounds__(256) void gemm_qkv(
    const float* __restrict__ x,
    const float* __restrict__ Wq, const float* __restrict__ Wk,
    const float* __restrict__ Wv,
    float* __restrict__ Qp, float* __restrict__ Kp, float* __restrict__ Vp)
{
    const int bx = blockIdx.x;
    if (bx < 16)      gemm_core(x, Wq, Qp, ND,   ND, bx,      blockIdx.y);
    else if (bx < 20) gemm_core(x, Wk, Kp, NDKV, ND, bx - 16, blockIdx.y);
    else              gemm_core(x, Wv, Vp, NDKV, ND, bx - 20, blockIdx.y);
}

__global__ __launch_bounds__(256) void gemm_out(
    const float* __restrict__ A, const float* __restrict__ B,
    float* __restrict__ C)
{
    gemm_core(A, B, C, ND, ND, blockIdx.x, blockIdx.y);
}

// ---------------------------------------------------------------------------
// MMA flash attention (tf32). Br=256 (8 warps x 32 rows = 2 m-frags/warp),
// Bc=64, dh=64. Each K/V b-fragment feeds 2 MMAs (16 FLOP/smem-byte).
// K triple-buffered via cp.async; V double-buffered LDG + transposed STS;
// Q staged once to smem then held in registers; softmax in registers (exp2).
// ---------------------------------------------------------------------------
#define FA_P     68
#define KBUF     (64 * FA_P)                 // 4352 floats
#define OFF_K0   0
#define OFF_V0   (3 * KBUF)                  // after 3 K buffers
#define OFF_QS   (5 * KBUF)                  // after 2 V buffers
#define FA2_SMEM ((5 * KBUF + 256 * FA_P) * (int)sizeof(float))   // 156672 B
#define NTILES   (NT / 64)                   // 32

__global__ __launch_bounds__(256) void flash_mma(
    const float* __restrict__ Q, const float* __restrict__ K,
    const float* __restrict__ V, float* __restrict__ O)
{
    extern __shared__ float sm[];
    float* Qs = sm + OFF_QS;   // 256 x 68

    const int tid  = threadIdx.x;
    const int warp = tid >> 5;
    const int lane = tid & 31;
    const int g    = lane >> 2;      // 0..7
    const int tq   = lane & 3;       // 0..3
    const int bh   = blockIdx.y;
    const int b    = bh >> 5;
    const int h    = bh & 31;
    const int hkv  = h >> 2;
    const int q0   = blockIdx.x * 256;

    const int krow = tid >> 2;          // 0..63
    const int kcol = (tid & 3) * 16;    // 0,16,32,48
    const int vrow = tid & 63;
    const int vcb  = (tid >> 6) * 16;

    // --- prologue: cp.async K tiles 0 and 1 (separate groups) ---
    {
        const float* s0 = K + (size_t)(b * NT + krow) * NDKV + hkv * NDH + kcol;
        #pragma unroll
        for (int i = 0; i < 4; i++)
            cp_async16(&sm[OFF_K0 + krow * FA_P + kcol + 4 * i], s0 + 4 * i);
        asm volatile("cp.async.commit_group;\n" ::: "memory");
        const float* s1 = s0 + (size_t)64 * NDKV;
        #pragma unroll
        for (int i = 0; i < 4; i++)
            cp_async16(&sm[OFF_K0 + KBUF + krow * FA_P + kcol + 4 * i], s1 + 4 * i);
        asm volatile("cp.async.commit_group;\n" ::: "memory");
    }
    // --- V tile 0: LDG into registers ---
    float4 vr[4];
    {
        const float* src = V + (size_t)(b * NT + vrow) * NDKV + hkv * NDH + vcb;
        #pragma unroll
        for (int i = 0; i < 4; i++) vr[i] = *(const float4*)(src + 4 * i);
    }
    // --- stage Q (scale folded with log2e), tf32-rounded: 256 rows ---
    const float QSC = 0.18033688011112042f;   // 0.125 * log2(e)
    {
        const float* src = Q + (size_t)(b * NT + q0 + tid) * ND + h * NDH;
        float* d = &Qs[tid * FA_P];
        #pragma unroll
        for (int i = 0; i < 16; i++) {
            float4 v = *(const float4*)(src + 4 * i);
            d[4 * i + 0] = to_tf32(QSC * v.x);
            d[4 * i + 1] = to_tf32(QSC * v.y);
            d[4 * i + 2] = to_tf32(QSC * v.z);
            d[4 * i + 3] = to_tf32(QSC * v.w);
        }
    }
    __syncthreads();

    // --- Q fragments into registers: 2 m-frags (rows warp*32+16f+g, +8) ---
    uint32_t qa[2][8][4];
    #pragma unroll
    for (int f = 0; f < 2; f++) {
        const float* qr0 = &Qs[(warp * 32 + 16 * f + g) * FA_P];
        const float* qr1 = qr0 + 8 * FA_P;
        #pragma unroll
        for (int ks = 0; ks < 8; ks++) {
            qa[f][ks][0] = __float_as_uint(qr0[8 * ks + tq]);
            qa[f][ks][1] = __float_as_uint(qr1[8 * ks + tq]);
            qa[f][ks][2] = __float_as_uint(qr0[8 * ks + tq + 4]);
            qa[f][ks][3] = __float_as_uint(qr1[8 * ks + tq + 4]);
        }
    }
    // --- STS V tile 0 (transposed, rounded) ---
    {
        float* dst = sm + OFF_V0;
        #pragma unroll
        for (int i = 0; i < 4; i++) {
            dst[(vcb + 4 * i + 0) * FA_P + vrow] = to_tf32(vr[i].x);
            dst[(vcb + 4 * i + 1) * FA_P + vrow] = to_tf32(vr[i].y);
            dst[(vcb + 4 * i + 2) * FA_P + vrow] = to_tf32(vr[i].z);
            dst[(vcb + 4 * i + 3) * FA_P + vrow] = to_tf32(vr[i].w);
        }
    }
    // --- LDG V tile 1 ---
    {
        const float* src = V + (size_t)(b * NT + 64 + vrow) * NDKV + hkv * NDH + vcb;
        #pragma unroll
        for (int i = 0; i < 4; i++) vr[i] = *(const float4*)(src + 4 * i);
    }
    __syncthreads();

    float mrow[2][2], lrow[2][2];
    #pragma unroll
    for (int f = 0; f < 2; f++) { mrow[f][0] = mrow[f][1] = -1e30f;
                                  lrow[f][0] = lrow[f][1] = 0.f; }
    float acc_o[2][8][4];
    #pragma unroll
    for (int f = 0; f < 2; f++)
        #pragma unroll
        for (int j = 0; j < 8; j++)
            #pragma unroll
            for (int r = 0; r < 4; r++) acc_o[f][j][r] = 0.f;

    const unsigned fm   = 0xffffffffu;
    const int      src0 = (lane & 28) | (tq >> 1);
    const int      src2 = src0 + 2;

    for (int kb = 0; kb < NTILES; kb++) {
        const int vb   = kb & 1;
        const bool pre1 = kb + 1 < NTILES;
        const bool pre2 = kb + 2 < NTILES;

        // ensure K(kb) landed (leave K(kb+1) in flight), then block barrier
        if (pre1) asm volatile("cp.async.wait_group 1;\n" ::: "memory");
        else      asm volatile("cp.async.wait_group 0;\n" ::: "memory");
        __syncthreads();

        // issue K(kb+2) into the third buffer (not read until kb+2)
        if (pre2) {
            float* kdst = sm + OFF_K0 + ((kb + 2) % 3) * KBUF;
            const float* src = K + (size_t)(b * NT + (kb + 2) * 64 + krow) * NDKV
                               + hkv * NDH + kcol;
            #pragma unroll
            for (int i = 0; i < 4; i++)
                cp_async16(&kdst[krow * FA_P + kcol + 4 * i], src + 4 * i);
            asm volatile("cp.async.commit_group;\n" ::: "memory");
        }

        // --- QK(kb): each b-frag feeds both m-frags ---
        float s[2][8][4];
        #pragma unroll
        for (int f = 0; f < 2; f++)
            #pragma unroll
            for (int j = 0; j < 8; j++)
                #pragma unroll
                for (int r = 0; r < 4; r++) s[f][j][r] = 0.f;
        {
            const float* kp = sm + OFF_K0 + (kb % 3) * KBUF;
            #pragma unroll
            for (int ks = 0; ks < 8; ks++)
                #pragma unroll
                for (int j = 0; j < 8; j++) {
                    const uint32_t b0 = __float_as_uint(kp[(8 * j + g) * FA_P + 8 * ks + tq]);
                    const uint32_t b1 = __float_as_uint(kp[(8 * j + g) * FA_P + 8 * ks + tq + 4]);
                    mma_tf32(s[0][j], qa[0][ks][0], qa[0][ks][1], qa[0][ks][2],
                             qa[0][ks][3], b0, b1);
                    mma_tf32(s[1][j], qa[1][ks][0], qa[1][ks][1], qa[1][ks][2],
                             qa[1][ks][3], b0, b1);
                }
        }

        // --- STS V(kb+1) (transposed); prior PV(kb-1) done at top barrier ---
        if (pre1) {
            float* dst = sm + OFF_V0 + (vb ^ 1) * KBUF;
            #pragma unroll
            for (int i = 0; i < 4; i++) {
                dst[(vcb + 4 * i + 0) * FA_P + vrow] = to_tf32(vr[i].x);
                dst[(vcb + 4 * i + 1) * FA_P + vrow] = to_tf32(vr[i].y);
                dst[(vcb + 4 * i + 2) * FA_P + vrow] = to_tf32(vr[i].z);
                dst[(vcb + 4 * i + 3) * FA_P + vrow] = to_tf32(vr[i].w);
            }
        }
        // --- LDG V(kb+2) into registers ---
        if (pre2) {
            const float* vsrc = V + (size_t)(b * NT + (kb + 2) * 64 + vrow) * NDKV
                                + hkv * NDH + vcb;
            #pragma unroll
            for (int i = 0; i < 4; i++) vr[i] = *(const float4*)(vsrc + 4 * i);
        }

        // --- online softmax (exp2 domain), both m-frags ---
        #pragma unroll
        for (int f = 0; f < 2; f++) {
            float mt0 = -1e30f, mt1 = -1e30f;
            #pragma unroll
            for (int j = 0; j < 8; j++) {
                mt0 = fmaxf(mt0, fmaxf(s[f][j][0], s[f][j][1]));
                mt1 = fmaxf(mt1, fmaxf(s[f][j][2], s[f][j][3]));
            }
            mt0 = fmaxf(mt0, __shfl_xor_sync(fm, mt0, 1));
            mt0 = fmaxf(mt0, __shfl_xor_sync(fm, mt0, 2));
            mt1 = fmaxf(mt1, __shfl_xor_sync(fm, mt1, 1));
            mt1 = fmaxf(mt1, __shfl_xor_sync(fm, mt1, 2));
            const float mn0 = fmaxf(mrow[f][0], mt0);
            const float mn1 = fmaxf(mrow[f][1], mt1);
            const float al0 = exp2f(mrow[f][0] - mn0);
            const float al1 = exp2f(mrow[f][1] - mn1);
            mrow[f][0] = mn0; mrow[f][1] = mn1;
            float rs0 = 0.f, rs1 = 0.f;
            #pragma unroll
            for (int j = 0; j < 8; j++) {
                s[f][j][0] = exp2f(s[f][j][0] - mn0); rs0 += s[f][j][0];
                s[f][j][1] = exp2f(s[f][j][1] - mn0); rs0 += s[f][j][1];
                s[f][j][2] = exp2f(s[f][j][2] - mn1); rs1 += s[f][j][2];
                s[f][j][3] = exp2f(s[f][j][3] - mn1); rs1 += s[f][j][3];
            }
            rs0 += __shfl_xor_sync(fm, rs0, 1);
            rs0 += __shfl_xor_sync(fm, rs0, 2);
            rs1 += __shfl_xor_sync(fm, rs1, 1);
            rs1 += __shfl_xor_sync(fm, rs1, 2);
            lrow[f][0] = lrow[f][0] * al0 + rs0;
            lrow[f][1] = lrow[f][1] * al1 + rs1;
            #pragma unroll
            for (int j = 0; j < 8; j++) {
                acc_o[f][j][0] *= al0; acc_o[f][j][1] *= al0;
                acc_o[f][j][2] *= al1; acc_o[f][j][3] *= al1;
            }
        }

        // --- PV(kb): b-frags shared across both m-frags ---
        {
            const float* vt = sm + OFF_V0 + vb * KBUF;
            const bool odd = tq & 1;
            #pragma unroll
            for (int ks = 0; ks < 8; ks++) {
                uint32_t pa[2][4];
                #pragma unroll
                for (int f = 0; f < 2; f++) {
                    const float e00 = __shfl_sync(fm, s[f][ks][0], src0);
                    const float e01 = __shfl_sync(fm, s[f][ks][1], src0);
                    const float e10 = __shfl_sync(fm, s[f][ks][2], src0);
                    const float e11 = __shfl_sync(fm, s[f][ks][3], src0);
                    const float e20 = __shfl_sync(fm, s[f][ks][0], src2);
                    const float e21 = __shfl_sync(fm, s[f][ks][1], src2);
                    const float e30 = __shfl_sync(fm, s[f][ks][2], src2);
                    const float e31 = __shfl_sync(fm, s[f][ks][3], src2);
                    pa[f][0] = __float_as_uint(to_tf32(odd ? e01 : e00));
                    pa[f][1] = __float_as_uint(to_tf32(odd ? e11 : e10));
                    pa[f][2] = __float_as_uint(to_tf32(odd ? e21 : e20));
                    pa[f][3] = __float_as_uint(to_tf32(odd ? e31 : e30));
                }
                #pragma unroll
                for (int jd = 0; jd < 8; jd++) {
                    const uint32_t b0 = __float_as_uint(vt[(8 * jd + g) * FA_P + 8 * ks + tq]);
                    const uint32_t b1 = __float_as_uint(vt[(8 * jd + g) * FA_P + 8 * ks + tq + 4]);
                    mma_tf32(acc_o[0][jd], pa[0][0], pa[0][1], pa[0][2], pa[0][3], b0, b1);
                    mma_tf32(acc_o[1][jd], pa[1][0], pa[1][1], pa[1][2], pa[1][3], b0, b1);
                }
            }
        }
    }

    // --- epilogue: normalize and store ---
    #pragma unroll
    for (int f = 0; f < 2; f++) {
        const float inv0 = 1.0f / lrow[f][0];
        const float inv1 = 1.0f / lrow[f][1];
        const size_t row0 = (size_t)(b * NT + q0 + warp * 32 + 16 * f + g);
        float* o0 = O + row0 * ND + h * NDH;
        float* o1 = o0 + (size_t)8 * ND;
        #pragma unroll
        for (int jd = 0; jd < 8; jd++) {
            *(float2*)(o0 + 8 * jd + 2 * tq) =
                make_float2(acc_o[f][jd][0] * inv0, acc_o[f][jd][1] * inv0);
            *(float2*)(o1 + 8 * jd + 2 * tq) =
                make_float2(acc_o[f][jd][2] * inv1, acc_o[f][jd][3] * inv1);
        }
    }
}

// ---------------------------------------------------------------------------
extern "C" void kernel_launch(void* const* d_in, const int* in_sizes, int n_in,
                              void* d_out, int out_size)
{
    const float* x  = (const float*)d_in[0];
    const float* Wq = (const float*)d_in[1];
    const float* Wk = (const float*)d_in[2];
    const float* Wv = (const float*)d_in[3];
    const float* Wo = (const float*)d_in[4];
    float* out = (float*)d_out;

    float *Qp, *Kp, *Vp, *Ap;
    cudaGetSymbolAddress((void**)&Qp, g_Q);
    cudaGetSymbolAddress((void**)&Kp, g_K);
    cudaGetSymbolAddress((void**)&Vp, g_V);
    cudaGetSymbolAddress((void**)&Ap, g_A);

    cudaFuncSetAttribute(flash_mma,
                         cudaFuncAttributeMaxDynamicSharedMemorySize, FA2_SMEM);

    gemm_qkv<<<dim3(24, 16), 256>>>(x, Wq, Wk, Wv, Qp, Kp, Vp);
    flash_mma<<<dim3(NT / 256, NB * NHQ), 256, FA2_SMEM>>>(Qp, Kp, Vp, Ap);
    gemm_out<<<dim3(16, 16), 256>>>(Ap, Wo, out);
}

// round 7
// speedup vs baseline: 1.2002x; 1.0982x over previous
#include <cuda_runtime.h>
#include <cstdint>

#define NB   2
#define NT   2048
#define ND   2048
#define NHQ  32
#define NHKV 8
#define NDH  64
#define NTOK (NB*NT)      // 4096
#define NDKV (NHKV*NDH)   // 512

// scratch (device globals: allocation-free per harness rules)
__device__ float g_Q[(size_t)NTOK * ND];     // 32 MB
__device__ float g_K[(size_t)NTOK * NDKV];   // 8 MB
__device__ float g_V[(size_t)NTOK * NDKV];   // 8 MB
__device__ float g_A[(size_t)NTOK * ND];     // 32 MB
// pre-rounded (tf32-valued) operand copies
__device__ float g_X [(size_t)NTOK * ND];    // 32 MB
__device__ float g_Wq[(size_t)ND * ND];      // 16 MB
__device__ float g_Wk[(size_t)ND * NDKV];    // 4 MB
__device__ float g_Wv[(size_t)ND * NDKV];    // 4 MB
__device__ float g_Wo[(size_t)ND * ND];      // 16 MB

// ---------------------------------------------------------------------------
__device__ __forceinline__ float to_tf32(float x) {
    float r;
    asm("cvt.rna.tf32.f32 %0, %1;" : "=f"(r) : "f"(x));
    return r;
}

__device__ __forceinline__ void mma_tf32(float* c, uint32_t a0, uint32_t a1,
                                         uint32_t a2, uint32_t a3,
                                         uint32_t b0, uint32_t b1) {
    asm volatile(
        "mma.sync.aligned.m16n8k8.row.col.f32.tf32.tf32.f32 "
        "{%0,%1,%2,%3}, {%4,%5,%6,%7}, {%8,%9}, {%0,%1,%2,%3};"
        : "+f"(c[0]), "+f"(c[1]), "+f"(c[2]), "+f"(c[3])
        : "r"(a0), "r"(a1), "r"(a2), "r"(a3), "r"(b0), "r"(b1));
}

__device__ __forceinline__ void cp_async16(void* smem_ptr, const void* gptr) {
    unsigned saddr = (unsigned)__cvta_generic_to_shared(smem_ptr);
    asm volatile("cp.async.cg.shared.global [%0], [%1], 16;\n"
                 :: "r"(saddr), "l"(gptr));
}

// ---------------------------------------------------------------------------
// prep: elementwise tf32 rounding (vectorized)
// ---------------------------------------------------------------------------
__global__ __launch_bounds__(256) void round_tf32(
    const float* __restrict__ in, float* __restrict__ out, int n4)
{
    int i = blockIdx.x * blockDim.x + threadIdx.x;
    if (i < n4) {
        float4 v = ((const float4*)in)[i];
        v.x = to_tf32(v.x); v.y = to_tf32(v.y);
        v.z = to_tf32(v.z); v.w = to_tf32(v.w);
        ((float4*)out)[i] = v;
    }
}

// ---------------------------------------------------------------------------
// tf32 GEMM: block 256x128, BK=16, 8 warps (4x2), warp tile 64x64.
// 3-stage cp.async pipeline; inputs must be pre-rounded to tf32 values.
// A staged [m][k] pitch 20 (all a-frag LDS patterns conflict-free),
// B staged [k][n] pitch 136. M%256==0, N%128==0, K%16==0.
// ---------------------------------------------------------------------------
#define GA_P   20
#define GS_A   (256 * GA_P)          // 5120 floats
#define GS_B   (16 * 136)            // 2176 floats
#define GSTG   (GS_A + GS_B)         // 7296 floats
#define G_SMEM (3 * GSTG * (int)sizeof(float))   // 87552 B

__device__ __forceinline__ void gemm_core(
    const float* __restrict__ A, const float* __restrict__ B,
    float* __restrict__ C, int N, int K, int bx, int by, float* gsm)
{
    const int tid  = threadIdx.x;
    const int warp = tid >> 5;
    const int lane = tid & 31;
    const int g    = lane >> 2;
    const int t    = lane & 3;
    const int mbase = (warp >> 1) * 64;   // 0,64,128,192
    const int nbase = (warp & 1) * 64;    // 0,64

    const float* Arow = A + (size_t)(by * 256 + tid) * K;       // one row/thread
    const float* Brow = B + (size_t)(tid >> 4) * N + bx * 128 + (tid & 15) * 8;
    const int a_off = tid * GA_P;
    const int b_off = (tid >> 4) * 136 + (tid & 15) * 8;

    const int iters = K / 16;

    // issue stage `it` into ring buffer it%3
    auto issue = [&](int it) {
        float* as = gsm + (it % 3) * GSTG;
        const float* asrc = Arow + it * 16;
        #pragma unroll
        for (int i = 0; i < 4; i++)
            cp_async16(&as[a_off + 4 * i], asrc + 4 * i);
        float* bs = as + GS_A;
        const float* bsrc = Brow + (size_t)(it * 16) * N;
        cp_async16(&bs[b_off],     bsrc);
        cp_async16(&bs[b_off + 4], bsrc + 4);
        asm volatile("cp.async.commit_group;\n" ::: "memory");
    };

    float acc[4][8][4];
    #pragma unroll
    for (int i = 0; i < 4; i++)
        #pragma unroll
        for (int j = 0; j < 8; j++)
            #pragma unroll
            for (int r = 0; r < 4; r++) acc[i][j][r] = 0.f;

    issue(0);
    if (iters > 1) issue(1);

    for (int it = 0; it < iters; it++) {
        if (it + 1 < iters)
            asm volatile("cp.async.wait_group 1;\n" ::: "memory");
        else
            asm volatile("cp.async.wait_group 0;\n" ::: "memory");
        __syncthreads();   // stage it landed; all warps done with stage it-1

        if (it + 2 < iters) issue(it + 2);   // overwrites buffer (it-1)%3

        const float* as = gsm + (it % 3) * GSTG;
        const float* bs = as + GS_A;

        #pragma unroll
        for (int ks = 0; ks < 16; ks += 8) {
            uint32_t af[4][4];
            #pragma unroll
            for (int mf = 0; mf < 4; mf++) {
                const int m0 = mbase + mf * 16 + g;
                af[mf][0] = __float_as_uint(as[(m0    ) * GA_P + ks + t]);
                af[mf][1] = __float_as_uint(as[(m0 + 8) * GA_P + ks + t]);
                af[mf][2] = __float_as_uint(as[(m0    ) * GA_P + ks + t + 4]);
                af[mf][3] = __float_as_uint(as[(m0 + 8) * GA_P + ks + t + 4]);
            }
            uint32_t bf[8][2];
            #pragma unroll
            for (int nf = 0; nf < 8; nf++) {
                const int n0 = nbase + nf * 8 + g;
                bf[nf][0] = __float_as_uint(bs[(ks + t    ) * 136 + n0]);
                bf[nf][1] = __float_as_uint(bs[(ks + t + 4) * 136 + n0]);
            }
            #pragma unroll
            for (int mf = 0; mf < 4; mf++)
                #pragma unroll
                for (int nf = 0; nf < 8; nf++)
                    mma_tf32(acc[mf][nf], af[mf][0], af[mf][1], af[mf][2],
                             af[mf][3], bf[nf][0], bf[nf][1]);
        }
        __syncthreads();   // done reading stage it before it gets overwritten
    }

    #pragma unroll
    for (int mf = 0; mf < 4; mf++) {
        const int row = by * 256 + mbase + mf * 16 + g;
        #pragma unroll
        for (int nf = 0; nf < 8; nf++) {
            const int col = bx * 128 + nbase + nf * 8 + 2 * t;
            *(float2*)(C + (size_t)row * N + col) =
                make_float2(acc[mf][nf][0], acc[mf][nf][1]);
            *(float2*)(C + (size_t)(row + 8) * N + col) =
                make_float2(acc[mf][nf][2], acc[mf][nf][3]);
        }
    }
}

// fused Q/K/V projection: grid (24, 16); bx<16 -> Q, <20 -> K, else -> V
__global__ __launch_bounds__(256) void gemm_qkv(
    const float* __restrict__ x,
    const float* __restrict__ Wq, const float* __restrict__ Wk,
    const float* __restrict__ Wv,
    float* __restrict__ Qp, float* __restrict__ Kp, float* __restrict__ Vp)
{
    extern __shared__ float gsm[];
    const int bx = blockIdx.x;
    if (bx < 16)      gemm_core(x, Wq, Qp, ND,   ND, bx,      blockIdx.y, gsm);
    else if (bx < 20) gemm_core(x, Wk, Kp, NDKV, ND, bx - 16, blockIdx.y, gsm);
    else              gemm_core(x, Wv, Vp, NDKV, ND, bx - 20, blockIdx.y, gsm);
}

__global__ __launch_bounds__(256) void gemm_out(
    const float* __restrict__ A, const float* __restrict__ B,
    float* __restrict__ C)
{
    extern __shared__ float gsm[];
    gemm_core(A, B, C, ND, ND, blockIdx.x, blockIdx.y, gsm);
}

// ---------------------------------------------------------------------------
// MMA flash attention (tf32). Br=256 (8 warps x 32 rows = 2 m-frags/warp),
// Bc=64, dh=64. K triple-buffered cp.async; V double-buffered LDG+trans STS;
// Q in registers; softmax in registers (exp2). Epilogue rounds A to tf32.
// ---------------------------------------------------------------------------
#define FA_P     68
#define KBUF     (64 * FA_P)
#define OFF_K0   0
#define OFF_V0   (3 * KBUF)
#define OFF_QS   (5 * KBUF)
#define FA2_SMEM ((5 * KBUF + 256 * FA_P) * (int)sizeof(float))   // 156672 B
#define NTILES   (NT / 64)

__global__ __launch_bounds__(256) void flash_mma(
    const float* __restrict__ Q, const float* __restrict__ K,
    const float* __restrict__ V, float* __restrict__ O)
{
    extern __shared__ float sm[];
    float* Qs = sm + OFF_QS;

    const int tid  = threadIdx.x;
    const int warp = tid >> 5;
    const int lane = tid & 31;
    const int g    = lane >> 2;
    const int tq   = lane & 3;
    const int bh   = blockIdx.y;
    const int b    = bh >> 5;
    const int h    = bh & 31;
    const int hkv  = h >> 2;
    const int q0   = blockIdx.x * 256;

    const int krow = tid >> 2;
    const int kcol = (tid & 3) * 16;
    const int vrow = tid & 63;
    const int vcb  = (tid >> 6) * 16;

    {
        const float* s0 = K + (size_t)(b * NT + krow) * NDKV + hkv * NDH + kcol;
        #pragma unroll
        for (int i = 0; i < 4; i++)
            cp_async16(&sm[OFF_K0 + krow * FA_P + kcol + 4 * i], s0 + 4 * i);
        asm volatile("cp.async.commit_group;\n" ::: "memory");
        const float* s1 = s0 + (size_t)64 * NDKV;
        #pragma unroll
        for (int i = 0; i < 4; i++)
            cp_async16(&sm[OFF_K0 + KBUF + krow * FA_P + kcol + 4 * i], s1 + 4 * i);
        asm volatile("cp.async.commit_group;\n" ::: "memory");
    }
    float4 vr[4];
    {
        const float* src = V + (size_t)(b * NT + vrow) * NDKV + hkv * NDH + vcb;
        #pragma unroll
        for (int i = 0; i < 4; i++) vr[i] = *(const float4*)(src + 4 * i);
    }
    const float QSC = 0.18033688011112042f;   // 0.125 * log2(e)
    {
        const float* src = Q + (size_t)(b * NT + q0 + tid) * ND + h * NDH;
        float* d = &Qs[tid * FA_P];
        #pragma unroll
        for (int i = 0; i < 16; i++) {
            float4 v = *(const float4*)(src + 4 * i);
            d[4 * i + 0] = to_tf32(QSC * v.x);
            d[4 * i + 1] = to_tf32(QSC * v.y);
            d[4 * i + 2] = to_tf32(QSC * v.z);
            d[4 * i + 3] = to_tf32(QSC * v.w);
        }
    }
    __syncthreads();

    uint32_t qa[2][8][4];
    #pragma unroll
    for (int f = 0; f < 2; f++) {
        const float* qr0 = &Qs[(warp * 32 + 16 * f + g) * FA_P];
        const float* qr1 = qr0 + 8 * FA_P;
        #pragma unroll
        for (int ks = 0; ks < 8; ks++) {
            qa[f][ks][0] = __float_as_uint(qr0[8 * ks + tq]);
            qa[f][ks][1] = __float_as_uint(qr1[8 * ks + tq]);
            qa[f][ks][2] = __float_as_uint(qr0[8 * ks + tq + 4]);
            qa[f][ks][3] = __float_as_uint(qr1[8 * ks + tq + 4]);
        }
    }
    {
        float* dst = sm + OFF_V0;
        #pragma unroll
        for (int i = 0; i < 4; i++) {
            dst[(vcb + 4 * i + 0) * FA_P + vrow] = to_tf32(vr[i].x);
            dst[(vcb + 4 * i + 1) * FA_P + vrow] = to_tf32(vr[i].y);
            dst[(vcb + 4 * i + 2) * FA_P + vrow] = to_tf32(vr[i].z);
            dst[(vcb + 4 * i + 3) * FA_P + vrow] = to_tf32(vr[i].w);
        }
    }
    {
        const float* src = V + (size_t)(b * NT + 64 + vrow) * NDKV + hkv * NDH + vcb;
        #pragma unroll
        for (int i = 0; i < 4; i++) vr[i] = *(const float4*)(src + 4 * i);
    }
    __syncthreads();

    float mrow[2][2], lrow[2][2];
    #pragma unroll
    for (int f = 0; f < 2; f++) { mrow[f][0] = mrow[f][1] = -1e30f;
                                  lrow[f][0] = lrow[f][1] = 0.f; }
    float acc_o[2][8][4];
    #pragma unroll
    for (int f = 0; f < 2; f++)
        #pragma unroll
        for (int j = 0; j < 8; j++)
            #pragma unroll
            for (int r = 0; r < 4; r++) acc_o[f][j][r] = 0.f;

    const unsigned fm   = 0xffffffffu;
    const int      src0 = (lane & 28) | (tq >> 1);
    const int      src2 = src0 + 2;

    for (int kb = 0; kb < NTILES; kb++) {
        const int vb   = kb & 1;
        const bool pre1 = kb + 1 < NTILES;
        const bool pre2 = kb + 2 < NTILES;

        if (pre1) asm volatile("cp.async.wait_group 1;\n" ::: "memory");
        else      asm volatile("cp.async.wait_group 0;\n" ::: "memory");
        __syncthreads();

        if (pre2) {
            float* kdst = sm + OFF_K0 + ((kb + 2) % 3) * KBUF;
            const float* src = K + (size_t)(b * NT + (kb + 2) * 64 + krow) * NDKV
                               + hkv * NDH + kcol;
            #pragma unroll
            for (int i = 0; i < 4; i++)
                cp_async16(&kdst[krow * FA_P + kcol + 4 * i], src + 4 * i);
            asm volatile("cp.async.commit_group;\n" ::: "memory");
        }

        float s[2][8][4];
        #pragma unroll
        for (int f = 0; f < 2; f++)
            #pragma unroll
            for (int j = 0; j < 8; j++)
                #pragma unroll
                for (int r = 0; r < 4; r++) s[f][j][r] = 0.f;
        {
            const float* kp = sm + OFF_K0 + (kb % 3) * KBUF;
            #pragma unroll
            for (int ks = 0; ks < 8; ks++)
                #pragma unroll
                for (int j = 0; j < 8; j++) {
                    const uint32_t b0 = __float_as_uint(kp[(8 * j + g) * FA_P + 8 * ks + tq]);
                    const uint32_t b1 = __float_as_uint(kp[(8 * j + g) * FA_P + 8 * ks + tq + 4]);
                    mma_tf32(s[0][j], qa[0][ks][0], qa[0][ks][1], qa[0][ks][2],
                             qa[0][ks][3], b0, b1);
                    mma_tf32(s[1][j], qa[1][ks][0], qa[1][ks][1], qa[1][ks][2],
                             qa[1][ks][3], b0, b1);
                }
        }

        if (pre1) {
            float* dst = sm + OFF_V0 + (vb ^ 1) * KBUF;
            #pragma unroll
            for (int i = 0; i < 4; i++) {
                dst[(vcb + 4 * i + 0) * FA_P + vrow] = to_tf32(vr[i].x);
                dst[(vcb + 4 * i + 1) * FA_P + vrow] = to_tf32(vr[i].y);
                dst[(vcb + 4 * i + 2) * FA_P + vrow] = to_tf32(vr[i].z);
                dst[(vcb + 4 * i + 3) * FA_P + vrow] = to_tf32(vr[i].w);
            }
        }
        if (pre2) {
            const float* vsrc = V + (size_t)(b * NT + (kb + 2) * 64 + vrow) * NDKV
                                + hkv * NDH + vcb;
            #pragma unroll
            for (int i = 0; i < 4; i++) vr[i] = *(const float4*)(vsrc + 4 * i);
        }

        #pragma unroll
        for (int f = 0; f < 2; f++) {
            float mt0 = -1e30f, mt1 = -1e30f;
            #pragma unroll
            for (int j = 0; j < 8; j++) {
                mt0 = fmaxf(mt0, fmaxf(s[f][j][0], s[f][j][1]));
                mt1 = fmaxf(mt1, fmaxf(s[f][j][2], s[f][j][3]));
            }
            mt0 = fmaxf(mt0, __shfl_xor_sync(fm, mt0, 1));
            mt0 = fmaxf(mt0, __shfl_xor_sync(fm, mt0, 2));
            mt1 = fmaxf(mt1, __shfl_xor_sync(fm, mt1, 1));
            mt1 = fmaxf(mt1, __shfl_xor_sync(fm, mt1, 2));
            const float mn0 = fmaxf(mrow[f][0], mt0);
            const float mn1 = fmaxf(mrow[f][1], mt1);
            const float al0 = exp2f(mrow[f][0] - mn0);
            const float al1 = exp2f(mrow[f][1] - mn1);
            mrow[f][0] = mn0; mrow[f][1] = mn1;
            float rs0 = 0.f, rs1 = 0.f;
            #pragma unroll
            for (int j = 0; j < 8; j++) {
                s[f][j][0] = exp2f(s[f][j][0] - mn0); rs0 += s[f][j][0];
                s[f][j][1] = exp2f(s[f][j][1] - mn0); rs0 += s[f][j][1];
                s[f][j][2] = exp2f(s[f][j][2] - mn1); rs1 += s[f][j][2];
                s[f][j][3] = exp2f(s[f][j][3] - mn1); rs1 += s[f][j][3];
            }
            rs0 += __shfl_xor_sync(fm, rs0, 1);
            rs0 += __shfl_xor_sync(fm, rs0, 2);
            rs1 += __shfl_xor_sync(fm, rs1, 1);
            rs1 += __shfl_xor_sync(fm, rs1, 2);
            lrow[f][0] = lrow[f][0] * al0 + rs0;
            lrow[f][1] = lrow[f][1] * al1 + rs1;
            #pragma unroll
            for (int j = 0; j < 8; j++) {
                acc_o[f][j][0] *= al0; acc_o[f][j][1] *= al0;
                acc_o[f][j][2] *= al1; acc_o[f][j][3] *= al1;
            }
        }

        {
            const float* vt = sm + OFF_V0 + vb * KBUF;
            const bool odd = tq & 1;
            #pragma unroll
            for (int ks = 0; ks < 8; ks++) {
                uint32_t pa[2][4];
                #pragma unroll
                for (int f = 0; f < 2; f++) {
                    const float e00 = __shfl_sync(fm, s[f][ks][0], src0);
                    const float e01 = __shfl_sync(fm, s[f][ks][1], src0);
                    const float e10 = __shfl_sync(fm, s[f][ks][2], src0);
                    const float e11 = __shfl_sync(fm, s[f][ks][3], src0);
                    const float e20 = __shfl_sync(fm, s[f][ks][0], src2);
                    const float e21 = __shfl_sync(fm, s[f][ks][1], src2);
                    const float e30 = __shfl_sync(fm, s[f][ks][2], src2);
                    const float e31 = __shfl_sync(fm, s[f][ks][3], src2);
                    pa[f][0] = __float_as_uint(to_tf32(odd ? e01 : e00));
                    pa[f][1] = __float_as_uint(to_tf32(odd ? e11 : e10));
                    pa[f][2] = __float_as_uint(to_tf32(odd ? e21 : e20));
                    pa[f][3] = __float_as_uint(to_tf32(odd ? e31 : e30));
                }
                #pragma unroll
                for (int jd = 0; jd < 8; jd++) {
                    const uint32_t b0 = __float_as_uint(vt[(8 * jd + g) * FA_P + 8 * ks + tq]);
                    const uint32_t b1 = __float_as_uint(vt[(8 * jd + g) * FA_P + 8 * ks + tq + 4]);
                    mma_tf32(acc_o[0][jd], pa[0][0], pa[0][1], pa[0][2], pa[0][3], b0, b1);
                    mma_tf32(acc_o[1][jd], pa[1][0], pa[1][1], pa[1][2], pa[1][3], b0, b1);
                }
            }
        }
    }

    // epilogue: normalize, round to tf32 (gemm_out consumes via cp.async), store
    #pragma unroll
    for (int f = 0; f < 2; f++) {
        const float inv0 = 1.0f / lrow[f][0];
        const float inv1 = 1.0f / lrow[f][1];
        const size_t row0 = (size_t)(b * NT + q0 + warp * 32 + 16 * f + g);
        float* o0 = O + row0 * ND + h * NDH;
        float* o1 = o0 + (size_t)8 * ND;
        #pragma unroll
        for (int jd = 0; jd < 8; jd++) {
            *(float2*)(o0 + 8 * jd + 2 * tq) =
                make_float2(to_tf32(acc_o[f][jd][0] * inv0),
                            to_tf32(acc_o[f][jd][1] * inv0));
            *(float2*)(o1 + 8 * jd + 2 * tq) =
                make_float2(to_tf32(acc_o[f][jd][2] * inv1),
                            to_tf32(acc_o[f][jd][3] * inv1));
        }
    }
}

// ---------------------------------------------------------------------------
extern "C" void kernel_launch(void* const* d_in, const int* in_sizes, int n_in,
                              void* d_out, int out_size)
{
    const float* x  = (const float*)d_in[0];
    const float* Wq = (const float*)d_in[1];
    const float* Wk = (const float*)d_in[2];
    const float* Wv = (const float*)d_in[3];
    const float* Wo = (const float*)d_in[4];
    float* out = (float*)d_out;

    float *Qp, *Kp, *Vp, *Ap, *Xr, *Wqr, *Wkr, *Wvr, *Wor;
    cudaGetSymbolAddress((void**)&Qp,  g_Q);
    cudaGetSymbolAddress((void**)&Kp,  g_K);
    cudaGetSymbolAddress((void**)&Vp,  g_V);
    cudaGetSymbolAddress((void**)&Ap,  g_A);
    cudaGetSymbolAddress((void**)&Xr,  g_X);
    cudaGetSymbolAddress((void**)&Wqr, g_Wq);
    cudaGetSymbolAddress((void**)&Wkr, g_Wk);
    cudaGetSymbolAddress((void**)&Wvr, g_Wv);
    cudaGetSymbolAddress((void**)&Wor, g_Wo);

    cudaFuncSetAttribute(flash_mma,
                         cudaFuncAttributeMaxDynamicSharedMemorySize, FA2_SMEM);
    cudaFuncSetAttribute(gemm_qkv,
                         cudaFuncAttributeMaxDynamicSharedMemorySize, G_SMEM);
    cudaFuncSetAttribute(gemm_out,
                         cudaFuncAttributeMaxDynamicSharedMemorySize, G_SMEM);

    // prep: tf32-round operands once (values identical to per-tile rounding)
    const int nX  = NTOK * ND / 4, nWq = ND * ND / 4, nWk = ND * NDKV / 4;
    round_tf32<<<(nX  + 255) / 256, 256>>>(x,  Xr,  nX);
    round_tf32<<<(nWq + 255) / 256, 256>>>(Wq, Wqr, nWq);
    round_tf32<<<(nWk + 255) / 256, 256>>>(Wk, Wkr, nWk);
    round_tf32<<<(nWk + 255) / 256, 256>>>(Wv, Wvr, nWk);
    round_tf32<<<(nWq + 255) / 256, 256>>>(Wo, Wor, nWq);

    gemm_qkv<<<dim3(24, 16), 256, G_SMEM>>>(Xr, Wqr, Wkr, Wvr, Qp, Kp, Vp);
    flash_mma<<<dim3(NT / 256, NB * NHQ), 256, FA2_SMEM>>>(Qp, Kp, Vp, Ap);
    gemm_out<<<dim3(16, 16), 256, G_SMEM>>>(Ap, Wor, out);
}

// round 8
// speedup vs baseline: 2.3362x; 1.9464x over previous
#include <cuda_runtime.h>
#include <cuda_fp16.h>
#include <cstdint>

#define NB   2
#define NT   2048
#define ND   2048
#define NHQ  32
#define NHKV 8
#define NDH  64
#define NTOK (NB*NT)      // 4096
#define NDKV (NHKV*NDH)   // 512

// fp16 scratch (device globals: allocation-free per harness rules)
__device__ __half g_Qh[(size_t)NTOK * ND];     // 16 MB
__device__ __half g_Kh[(size_t)NTOK * NDKV];   // 4 MB
__device__ __half g_Vh[(size_t)NTOK * NDKV];   // 4 MB
__device__ __half g_Ah[(size_t)NTOK * ND];     // 16 MB
__device__ __half g_Xh[(size_t)NTOK * ND];     // 16 MB
__device__ __half g_WqT[(size_t)ND * ND];      // 8 MB  [N][K]
__device__ __half g_WkT[(size_t)NDKV * ND];    // 2 MB
__device__ __half g_WvT[(size_t)NDKV * ND];    // 2 MB
__device__ __half g_WoT[(size_t)ND * ND];      // 8 MB

// ---------------------------------------------------------------------------
__device__ __forceinline__ void mma_f16(float* c, uint32_t a0, uint32_t a1,
                                        uint32_t a2, uint32_t a3,
                                        uint32_t b0, uint32_t b1) {
    asm volatile(
        "mma.sync.aligned.m16n8k16.row.col.f32.f16.f16.f32 "
        "{%0,%1,%2,%3}, {%4,%5,%6,%7}, {%8,%9}, {%0,%1,%2,%3};"
        : "+f"(c[0]), "+f"(c[1]), "+f"(c[2]), "+f"(c[3])
        : "r"(a0), "r"(a1), "r"(a2), "r"(a3), "r"(b0), "r"(b1));
}

__device__ __forceinline__ void cp_async16(void* smem_ptr, const void* gptr) {
    unsigned saddr = (unsigned)__cvta_generic_to_shared(smem_ptr);
    asm volatile("cp.async.cg.shared.global [%0], [%1], 16;\n"
                 :: "r"(saddr), "l"(gptr));
}

__device__ __forceinline__ uint32_t pack_half2(float lo, float hi) {
    uint32_t r;
    asm("cvt.rn.f16x2.f32 %0, %2, %1;" : "=r"(r) : "f"(lo), "f"(hi));
    return r;
}

// ---------------------------------------------------------------------------
// prep kernels
// ---------------------------------------------------------------------------
__global__ __launch_bounds__(256) void cvt_half(
    const float* __restrict__ in, __half* __restrict__ out, int n4)
{
    int i = blockIdx.x * blockDim.x + threadIdx.x;
    if (i < n4) {
        float4 v = ((const float4*)in)[i];
        __half2* o = (__half2*)(out + 4 * (size_t)i);
        o[0] = __floats2half2_rn(v.x, v.y);
        o[1] = __floats2half2_rn(v.z, v.w);
    }
}

// in: fp32 [R][C] row-major -> out: fp16 [C][R]
__global__ __launch_bounds__(256) void transpose_half(
    const float* __restrict__ in, __half* __restrict__ out, int R, int C)
{
    __shared__ float t[32][33];
    const int tx = threadIdx.x & 31;
    const int ty = threadIdx.x >> 5;     // 0..7
    const int r0 = blockIdx.y * 32;
    const int c0 = blockIdx.x * 32;
    #pragma unroll
    for (int i = 0; i < 32; i += 8)
        t[ty + i][tx] = in[(size_t)(r0 + ty + i) * C + c0 + tx];
    __syncthreads();
    #pragma unroll
    for (int i = 0; i < 32; i += 8)
        out[(size_t)(c0 + ty + i) * R + r0 + tx] = __float2half_rn(t[tx][ty + i]);
}

// ---------------------------------------------------------------------------
// fp16 GEMM: C[M,N] = A[M,K] @ B[K,N] with A fp16 [M][K], BT fp16 [N][K].
// Block 256x128, BK=32, 8 warps (4x2), warp tile 64x64, m16n8k16.
// 3-stage cp.async. Smem pitch 20 u32/row -> all frag LDS conflict-free.
// ---------------------------------------------------------------------------
#define GP     20                       // u32 pitch per row (16 used + 4 pad)
#define GS_A   (256 * GP)               // 5120 u32
#define GS_B   (128 * GP)               // 2560 u32
#define GSTG   (GS_A + GS_B)            // 7680 u32
#define G_SMEM (3 * GSTG * (int)sizeof(uint32_t))   // 92160 B

__device__ __forceinline__ void gemm_core_h(
    const __half* __restrict__ A, const __half* __restrict__ BT,
    void* __restrict__ C, bool half_out, int N, int K, int bx, int by,
    uint32_t* gsm)
{
    const int tid  = threadIdx.x;
    const int warp = tid >> 5;
    const int lane = tid & 31;
    const int g    = lane >> 2;
    const int t    = lane & 3;
    const int mbase = (warp >> 1) * 64;
    const int nbase = (warp & 1) * 64;

    const __half* Arow = A  + (size_t)(by * 256 + tid) * K;
    const __half* Brow = BT + (size_t)(bx * 128 + (tid >> 1)) * K + (tid & 1) * 16;
    const int a_off = tid * GP;
    const int b_off = (tid >> 1) * GP + (tid & 1) * 8;

    const int iters = K / 32;

    auto issue = [&](int it) {
        uint32_t* as = gsm + (it % 3) * GSTG;
        const __half* asrc = Arow + it * 32;
        #pragma unroll
        for (int i = 0; i < 4; i++)
            cp_async16(&as[a_off + 4 * i], asrc + 8 * i);
        uint32_t* bs = as + GS_A;
        const __half* bsrc = Brow + it * 32;
        cp_async16(&bs[b_off],     bsrc);
        cp_async16(&bs[b_off + 4], bsrc + 8);
        asm volatile("cp.async.commit_group;\n" ::: "memory");
    };

    float acc[4][8][4];
    #pragma unroll
    for (int i = 0; i < 4; i++)
        #pragma unroll
        for (int j = 0; j < 8; j++)
            #pragma unroll
            for (int r = 0; r < 4; r++) acc[i][j][r] = 0.f;

    issue(0);
    if (iters > 1) issue(1);

    for (int it = 0; it < iters; it++) {
        if (it + 1 < iters)
            asm volatile("cp.async.wait_group 1;\n" ::: "memory");
        else
            asm volatile("cp.async.wait_group 0;\n" ::: "memory");
        __syncthreads();

        if (it + 2 < iters) issue(it + 2);

        const uint32_t* as = gsm + (it % 3) * GSTG;
        const uint32_t* bs = as + GS_A;

        #pragma unroll
        for (int kc = 0; kc < 2; kc++) {
            uint32_t af[4][4];
            #pragma unroll
            for (int mf = 0; mf < 4; mf++) {
                const int m0 = mbase + mf * 16 + g;
                af[mf][0] = as[(m0    ) * GP + 8 * kc + t];
                af[mf][1] = as[(m0 + 8) * GP + 8 * kc + t];
                af[mf][2] = as[(m0    ) * GP + 8 * kc + t + 4];
                af[mf][3] = as[(m0 + 8) * GP + 8 * kc + t + 4];
            }
            uint32_t bf[8][2];
            #pragma unroll
            for (int nf = 0; nf < 8; nf++) {
                const int n0 = nbase + nf * 8 + g;
                bf[nf][0] = bs[n0 * GP + 8 * kc + t];
                bf[nf][1] = bs[n0 * GP + 8 * kc + t + 4];
            }
            #pragma unroll
            for (int mf = 0; mf < 4; mf++)
                #pragma unroll
                for (int nf = 0; nf < 8; nf++)
                    mma_f16(acc[mf][nf], af[mf][0], af[mf][1], af[mf][2],
                            af[mf][3], bf[nf][0], bf[nf][1]);
        }
        __syncthreads();
    }

    #pragma unroll
    for (int mf = 0; mf < 4; mf++) {
        const int row = by * 256 + mbase + mf * 16 + g;
        #pragma unroll
        for (int nf = 0; nf < 8; nf++) {
            const int col = bx * 128 + nbase + nf * 8 + 2 * t;
            if (half_out) {
                __half* Ch = (__half*)C;
                *(uint32_t*)(Ch + (size_t)row * N + col) =
                    pack_half2(acc[mf][nf][0], acc[mf][nf][1]);
                *(uint32_t*)(Ch + (size_t)(row + 8) * N + col) =
                    pack_half2(acc[mf][nf][2], acc[mf][nf][3]);
            } else {
                float* Cf = (float*)C;
                *(float2*)(Cf + (size_t)row * N + col) =
                    make_float2(acc[mf][nf][0], acc[mf][nf][1]);
                *(float2*)(Cf + (size_t)(row + 8) * N + col) =
                    make_float2(acc[mf][nf][2], acc[mf][nf][3]);
            }
        }
    }
}

__global__ __launch_bounds__(256) void gemm_qkv(
    const __half* __restrict__ x,
    const __half* __restrict__ WqT, const __half* __restrict__ WkT,
    const __half* __restrict__ WvT,
    __half* __restrict__ Qp, __half* __restrict__ Kp, __half* __restrict__ Vp)
{
    extern __shared__ uint32_t gsm[];
    const int bx = blockIdx.x;
    if (bx < 16)      gemm_core_h(x, WqT, Qp, true, ND,   ND, bx,      blockIdx.y, gsm);
    else if (bx < 20) gemm_core_h(x, WkT, Kp, true, NDKV, ND, bx - 16, blockIdx.y, gsm);
    else              gemm_core_h(x, WvT, Vp, true, NDKV, ND, bx - 20, blockIdx.y, gsm);
}

__global__ __launch_bounds__(256) void gemm_out(
    const __half* __restrict__ A, const __half* __restrict__ BT,
    float* __restrict__ C)
{
    extern __shared__ uint32_t gsm[];
    gemm_core_h(A, BT, C, false, ND, ND, blockIdx.x, blockIdx.y, gsm);
}

// ---------------------------------------------------------------------------
// fp16 MMA flash attention. Br=256 (8 warps x 32 rows = 2 m-frags/warp),
// Bc=64, dh=64, m16n8k16. Q frags LDG'd direct to regs; K triple-buffered
// cp.async (natural [t][d] layout IS the transposed-B pattern); V double-
// buffered LDG + half2(t,t+1)-packed transposed STS. Softmax fp32/exp2.
// P->A-frag is pure local register packing (no shuffles).
// Smem rows pitch 36 u32 -> all accesses conflict-free.
// ---------------------------------------------------------------------------
#define FP       36                      // u32 pitch (32 used + 4 pad)
#define KBUF     (64 * FP)               // 2304 u32 per tile buffer
#define FA_SMEM  (5 * KBUF * (int)sizeof(uint32_t))   // 46080 B
#define NTILES   (NT / 64)

__global__ __launch_bounds__(256) void flash_h(
    const __half* __restrict__ Q, const __half* __restrict__ K,
    const __half* __restrict__ V, __half* __restrict__ O)
{
    extern __shared__ uint32_t sm[];
    // layout: K bufs 0..2 at sm + i*KBUF; V bufs at sm + (3+vb)*KBUF

    const int tid  = threadIdx.x;
    const int warp = tid >> 5;
    const int lane = tid & 31;
    const int g    = lane >> 2;
    const int tq   = lane & 3;
    const int bh   = blockIdx.y;
    const int b    = bh >> 5;
    const int h    = bh & 31;
    const int hkv  = h >> 2;
    const int q0   = blockIdx.x * 256;

    const int krow = tid >> 2;           // 0..63 (t)
    const int kq   = tid & 3;            // 32B quarter
    const int vt2  = tid & 31;           // t-pair index
    const int vdb  = (tid >> 5) * 8;     // d block

    // --- prologue: cp.async K tiles 0,1 ---
    {
        const __half* s0 = K + (size_t)(b * NT + krow) * NDKV + hkv * NDH + kq * 16;
        cp_async16(&sm[krow * FP + kq * 8],     s0);
        cp_async16(&sm[krow * FP + kq * 8 + 4], s0 + 8);
        asm volatile("cp.async.commit_group;\n" ::: "memory");
        const __half* s1 = s0 + (size_t)64 * NDKV;
        cp_async16(&sm[KBUF + krow * FP + kq * 8],     s1);
        cp_async16(&sm[KBUF + krow * FP + kq * 8 + 4], s1 + 8);
        asm volatile("cp.async.commit_group;\n" ::: "memory");
    }
    // --- V tile 0 into regs (2 adjacent t rows x 8 d) ---
    uint4 v0, v1;
    {
        const __half* src = V + (size_t)(b * NT + 2 * vt2) * NDKV + hkv * NDH + vdb;
        v0 = *(const uint4*)(src);
        v1 = *(const uint4*)(src + NDKV);
    }
    // --- Q fragments direct LDG (scaled by 0.125*log2e) ---
    const float QSC = 0.18033688011112042f;
    const __half2 qsc2 = __float2half2_rn(QSC);
    uint32_t qa[2][4][4];
    {
        #pragma unroll
        for (int f = 0; f < 2; f++) {
            const size_t r0 = (size_t)(b * NT + q0 + warp * 32 + 16 * f + g);
            const uint32_t* p0 = (const uint32_t*)(Q + r0 * ND + h * NDH);
            const uint32_t* p1 = (const uint32_t*)(Q + (r0 + 8) * ND + h * NDH);
            #pragma unroll
            for (int kc = 0; kc < 4; kc++) {
                qa[f][kc][0] = p0[8 * kc + tq];
                qa[f][kc][1] = p1[8 * kc + tq];
                qa[f][kc][2] = p0[8 * kc + tq + 4];
                qa[f][kc][3] = p1[8 * kc + tq + 4];
                #pragma unroll
                for (int r = 0; r < 4; r++) {
                    __half2 hv = __hmul2(*(const __half2*)&qa[f][kc][r], qsc2);
                    qa[f][kc][r] = *(const uint32_t*)&hv;
                }
            }
        }
    }
    // --- STS V tile 0 (transposed, t-pairs packed) ---
    {
        uint32_t* dst = sm + 3 * KBUF;
        const __half* h0 = (const __half*)&v0;
        const __half* h1 = (const __half*)&v1;
        #pragma unroll
        for (int i = 0; i < 8; i++) {
            __half2 p = __halves2half2(h0[i], h1[i]);
            dst[(vdb + i) * FP + vt2] = *(const uint32_t*)&p;
        }
    }
    // --- LDG V tile 1 ---
    {
        const __half* src = V + (size_t)(b * NT + 64 + 2 * vt2) * NDKV + hkv * NDH + vdb;
        v0 = *(const uint4*)(src);
        v1 = *(const uint4*)(src + NDKV);
    }
    __syncthreads();

    float mrow[2][2], lrow[2][2];
    #pragma unroll
    for (int f = 0; f < 2; f++) { mrow[f][0] = mrow[f][1] = -1e30f;
                                  lrow[f][0] = lrow[f][1] = 0.f; }
    float acc_o[2][8][4];
    #pragma unroll
    for (int f = 0; f < 2; f++)
        #pragma unroll
        for (int j = 0; j < 8; j++)
            #pragma unroll
            for (int r = 0; r < 4; r++) acc_o[f][j][r] = 0.f;

    const unsigned fm = 0xffffffffu;

    for (int kb = 0; kb < NTILES; kb++) {
        const int vb   = kb & 1;
        const bool pre1 = kb + 1 < NTILES;
        const bool pre2 = kb + 2 < NTILES;

        if (pre1) asm volatile("cp.async.wait_group 1;\n" ::: "memory");
        else      asm volatile("cp.async.wait_group 0;\n" ::: "memory");
        __syncthreads();

        if (pre2) {
            uint32_t* kdst = sm + ((kb + 2) % 3) * KBUF;
            const __half* src = K + (size_t)(b * NT + (kb + 2) * 64 + krow) * NDKV
                                + hkv * NDH + kq * 16;
            cp_async16(&kdst[krow * FP + kq * 8],     src);
            cp_async16(&kdst[krow * FP + kq * 8 + 4], src + 8);
            asm volatile("cp.async.commit_group;\n" ::: "memory");
        }

        // --- QK(kb): S[f][q16][t64] ---
        float s[2][8][4];
        #pragma unroll
        for (int f = 0; f < 2; f++)
            #pragma unroll
            for (int j = 0; j < 8; j++)
                #pragma unroll
                for (int r = 0; r < 4; r++) s[f][j][r] = 0.f;
        {
            const uint32_t* kp = sm + (kb % 3) * KBUF;
            #pragma unroll
            for (int kc = 0; kc < 4; kc++)
                #pragma unroll
                for (int j = 0; j < 8; j++) {
                    const uint32_t b0 = kp[(8 * j + g) * FP + 8 * kc + tq];
                    const uint32_t b1 = kp[(8 * j + g) * FP + 8 * kc + tq + 4];
                    mma_f16(s[0][j], qa[0][kc][0], qa[0][kc][1], qa[0][kc][2],
                            qa[0][kc][3], b0, b1);
                    mma_f16(s[1][j], qa[1][kc][0], qa[1][kc][1], qa[1][kc][2],
                            qa[1][kc][3], b0, b1);
                }
        }

        // --- STS V(kb+1) ---
        if (pre1) {
            uint32_t* dst = sm + (3 + (vb ^ 1)) * KBUF;
            const __half* h0 = (const __half*)&v0;
            const __half* h1 = (const __half*)&v1;
            #pragma unroll
            for (int i = 0; i < 8; i++) {
                __half2 p = __halves2half2(h0[i], h1[i]);
                dst[(vdb + i) * FP + vt2] = *(const uint32_t*)&p;
            }
        }
        // --- LDG V(kb+2) ---
        if (pre2) {
            const __half* src = V + (size_t)(b * NT + (kb + 2) * 64 + 2 * vt2) * NDKV
                                + hkv * NDH + vdb;
            v0 = *(const uint4*)(src);
            v1 = *(const uint4*)(src + NDKV);
        }

        // --- online softmax (fp32, exp2 domain) ---
        #pragma unroll
        for (int f = 0; f < 2; f++) {
            float mt0 = -1e30f, mt1 = -1e30f;
            #pragma unroll
            for (int j = 0; j < 8; j++) {
                mt0 = fmaxf(mt0, fmaxf(s[f][j][0], s[f][j][1]));
                mt1 = fmaxf(mt1, fmaxf(s[f][j][2], s[f][j][3]));
            }
            mt0 = fmaxf(mt0, __shfl_xor_sync(fm, mt0, 1));
            mt0 = fmaxf(mt0, __shfl_xor_sync(fm, mt0, 2));
            mt1 = fmaxf(mt1, __shfl_xor_sync(fm, mt1, 1));
            mt1 = fmaxf(mt1, __shfl_xor_sync(fm, mt1, 2));
            const float mn0 = fmaxf(mrow[f][0], mt0);
            const float mn1 = fmaxf(mrow[f][1], mt1);
            const float al0 = exp2f(mrow[f][0] - mn0);
            const float al1 = exp2f(mrow[f][1] - mn1);
            mrow[f][0] = mn0; mrow[f][1] = mn1;
            float rs0 = 0.f, rs1 = 0.f;
            #pragma unroll
            for (int j = 0; j < 8; j++) {
                s[f][j][0] = exp2f(s[f][j][0] - mn0); rs0 += s[f][j][0];
                s[f][j][1] = exp2f(s[f][j][1] - mn0); rs0 += s[f][j][1];
                s[f][j][2] = exp2f(s[f][j][2] - mn1); rs1 += s[f][j][2];
                s[f][j][3] = exp2f(s[f][j][3] - mn1); rs1 += s[f][j][3];
            }
            rs0 += __shfl_xor_sync(fm, rs0, 1);
            rs0 += __shfl_xor_sync(fm, rs0, 2);
            rs1 += __shfl_xor_sync(fm, rs1, 1);
            rs1 += __shfl_xor_sync(fm, rs1, 2);
            lrow[f][0] = lrow[f][0] * al0 + rs0;
            lrow[f][1] = lrow[f][1] * al1 + rs1;
            #pragma unroll
            for (int j = 0; j < 8; j++) {
                acc_o[f][j][0] *= al0; acc_o[f][j][1] *= al0;
                acc_o[f][j][2] *= al1; acc_o[f][j][3] *= al1;
            }
        }

        // --- PV(kb): P packed locally to fp16 A-frags (no shuffles) ---
        {
            const uint32_t* vt = sm + (3 + vb) * KBUF;
            #pragma unroll
            for (int kc = 0; kc < 4; kc++) {
                uint32_t pa[2][4];
                #pragma unroll
                for (int f = 0; f < 2; f++) {
                    pa[f][0] = pack_half2(s[f][2 * kc][0],     s[f][2 * kc][1]);
                    pa[f][1] = pack_half2(s[f][2 * kc][2],     s[f][2 * kc][3]);
                    pa[f][2] = pack_half2(s[f][2 * kc + 1][0], s[f][2 * kc + 1][1]);
                    pa[f][3] = pack_half2(s[f][2 * kc + 1][2], s[f][2 * kc + 1][3]);
                }
                #pragma unroll
                for (int jd = 0; jd < 8; jd++) {
                    const uint32_t b0 = vt[(8 * jd + g) * FP + 8 * kc + tq];
                    const uint32_t b1 = vt[(8 * jd + g) * FP + 8 * kc + tq + 4];
                    mma_f16(acc_o[0][jd], pa[0][0], pa[0][1], pa[0][2], pa[0][3], b0, b1);
                    mma_f16(acc_o[1][jd], pa[1][0], pa[1][1], pa[1][2], pa[1][3], b0, b1);
                }
            }
        }
    }

    // --- epilogue: normalize, pack fp16, store ---
    #pragma unroll
    for (int f = 0; f < 2; f++) {
        const float inv0 = 1.0f / lrow[f][0];
        const float inv1 = 1.0f / lrow[f][1];
        const size_t r0 = (size_t)(b * NT + q0 + warp * 32 + 16 * f + g);
        __half* o0 = O + r0 * ND + h * NDH;
        __half* o1 = o0 + (size_t)8 * ND;
        #pragma unroll
        for (int jd = 0; jd < 8; jd++) {
            *(uint32_t*)(o0 + 8 * jd + 2 * tq) =
                pack_half2(acc_o[f][jd][0] * inv0, acc_o[f][jd][1] * inv0);
            *(uint32_t*)(o1 + 8 * jd + 2 * tq) =
                pack_half2(acc_o[f][jd][2] * inv1, acc_o[f][jd][3] * inv1);
        }
    }
}

// ---------------------------------------------------------------------------
extern "C" void kernel_launch(void* const* d_in, const int* in_sizes, int n_in,
                              void* d_out, int out_size)
{
    const float* x  = (const float*)d_in[0];
    const float* Wq = (const float*)d_in[1];
    const float* Wk = (const float*)d_in[2];
    const float* Wv = (const float*)d_in[3];
    const float* Wo = (const float*)d_in[4];
    float* out = (float*)d_out;

    __half *Qh, *Kh, *Vh, *Ah, *Xh, *WqT, *WkT, *WvT, *WoT;
    cudaGetSymbolAddress((void**)&Qh,  g_Qh);
    cudaGetSymbolAddress((void**)&Kh,  g_Kh);
    cudaGetSymbolAddress((void**)&Vh,  g_Vh);
    cudaGetSymbolAddress((void**)&Ah,  g_Ah);
    cudaGetSymbolAddress((void**)&Xh,  g_Xh);
    cudaGetSymbolAddress((void**)&WqT, g_WqT);
    cudaGetSymbolAddress((void**)&WkT, g_WkT);
    cudaGetSymbolAddress((void**)&WvT, g_WvT);
    cudaGetSymbolAddress((void**)&WoT, g_WoT);

    cudaFuncSetAttribute(flash_h,
                         cudaFuncAttributeMaxDynamicSharedMemorySize, FA_SMEM);
    cudaFuncSetAttribute(gemm_qkv,
                         cudaFuncAttributeMaxDynamicSharedMemorySize, G_SMEM);
    cudaFuncSetAttribute(gemm_out,
                         cudaFuncAttributeMaxDynamicSharedMemorySize, G_SMEM);

    // prep: x -> fp16, W -> transposed fp16
    const int nX = NTOK * ND / 4;
    cvt_half<<<(nX + 255) / 256, 256>>>(x, Xh, nX);
    transpose_half<<<dim3(ND / 32,   ND / 32), 256>>>(Wq, WqT, ND, ND);
    transpose_half<<<dim3(NDKV / 32, ND / 32), 256>>>(Wk, WkT, ND, NDKV);
    transpose_half<<<dim3(NDKV / 32, ND / 32), 256>>>(Wv, WvT, ND, NDKV);
    transpose_half<<<dim3(ND / 32,   ND / 32), 256>>>(Wo, WoT, ND, ND);

    gemm_qkv<<<dim3(24, 16), 256, G_SMEM>>>(Xh, WqT, WkT, WvT, Qh, Kh, Vh);
    flash_h<<<dim3(NT / 256, NB * NHQ), 256, FA_SMEM>>>(Qh, Kh, Vh, Ah);
    gemm_out<<<dim3(16, 16), 256, G_SMEM>>>(Ah, WoT, out);
}

// round 10
// speedup vs baseline: 2.5704x; 1.1002x over previous
#include <cuda_runtime.h>
#include <cuda_fp16.h>
#include <cstdint>

#define NB   2
#define NT   2048
#define ND   2048
#define NHQ  32
#define NHKV 8
#define NDH  64
#define NTOK (NB*NT)      // 4096
#define NDKV (NHKV*NDH)   // 512

// fp16 scratch (device globals: allocation-free per harness rules)
__device__ __half g_Qh[(size_t)NTOK * ND];     // 16 MB
__device__ __half g_Kh[(size_t)NTOK * NDKV];   // 4 MB
__device__ __half g_Vh[(size_t)NTOK * NDKV];   // 4 MB
__device__ __half g_Ah[(size_t)NTOK * ND];     // 16 MB
__device__ __half g_Xh[(size_t)NTOK * ND];     // 16 MB
__device__ __half g_WqT[(size_t)ND * ND];      // 8 MB  [N][K]
__device__ __half g_WkT[(size_t)NDKV * ND];    // 2 MB
__device__ __half g_WvT[(size_t)NDKV * ND];    // 2 MB
__device__ __half g_WoT[(size_t)ND * ND];      // 8 MB

// ---------------------------------------------------------------------------
__device__ __forceinline__ void mma_f16(float* c, uint32_t a0, uint32_t a1,
                                        uint32_t a2, uint32_t a3,
                                        uint32_t b0, uint32_t b1) {
    asm volatile(
        "mma.sync.aligned.m16n8k16.row.col.f32.f16.f16.f32 "
        "{%0,%1,%2,%3}, {%4,%5,%6,%7}, {%8,%9}, {%0,%1,%2,%3};"
        : "+f"(c[0]), "+f"(c[1]), "+f"(c[2]), "+f"(c[3])
        : "r"(a0), "r"(a1), "r"(a2), "r"(a3), "r"(b0), "r"(b1));
}

__device__ __forceinline__ void cp_async16(void* smem_ptr, const void* gptr) {
    unsigned saddr = (unsigned)__cvta_generic_to_shared(smem_ptr);
    asm volatile("cp.async.cg.shared.global [%0], [%1], 16;\n"
                 :: "r"(saddr), "l"(gptr));
}

__device__ __forceinline__ uint32_t pack_half2(float lo, float hi) {
    uint32_t r;
    asm("cvt.rn.f16x2.f32 %0, %2, %1;" : "=r"(r) : "f"(lo), "f"(hi));
    return r;
}

// ---------------------------------------------------------------------------
// prep kernels
// ---------------------------------------------------------------------------
__global__ __launch_bounds__(256) void cvt_half(
    const float* __restrict__ in, __half* __restrict__ out, int n4)
{
    int i = blockIdx.x * blockDim.x + threadIdx.x;
    if (i < n4) {
        float4 v = ((const float4*)in)[i];
        __half2* o = (__half2*)(out + 4 * (size_t)i);
        o[0] = __floats2half2_rn(v.x, v.y);
        o[1] = __floats2half2_rn(v.z, v.w);
    }
}

// fused transpose of all 4 weights: z selects matrix. in fp32 [R][C] -> out fp16 [C][R]
__global__ __launch_bounds__(256) void transpose4(
    const float* __restrict__ Wq, const float* __restrict__ Wk,
    const float* __restrict__ Wv, const float* __restrict__ Wo,
    __half* __restrict__ WqT, __half* __restrict__ WkT,
    __half* __restrict__ WvT, __half* __restrict__ WoT)
{
    const int z = blockIdx.z;
    const float* in;
    __half* out;
    int C;
    if (z == 0)      { in = Wq; out = WqT; C = ND; }
    else if (z == 1) { in = Wk; out = WkT; C = NDKV; }
    else if (z == 2) { in = Wv; out = WvT; C = NDKV; }
    else             { in = Wo; out = WoT; C = ND; }
    const int c0 = blockIdx.x * 32;
    if (c0 >= C) return;
    const int R = ND;
    const int r0 = blockIdx.y * 32;

    __shared__ float t[32][33];
    const int tx = threadIdx.x & 31;
    const int ty = threadIdx.x >> 5;
    #pragma unroll
    for (int i = 0; i < 32; i += 8)
        t[ty + i][tx] = in[(size_t)(r0 + ty + i) * C + c0 + tx];
    __syncthreads();
    #pragma unroll
    for (int i = 0; i < 32; i += 8)
        out[(size_t)(c0 + ty + i) * R + r0 + tx] = __float2half_rn(t[tx][ty + i]);
}

// ---------------------------------------------------------------------------
// fp16 GEMM: C[M,N] = A[M,K] @ B[K,N], A fp16 [M][K], BT fp16 [N][K].
// Block 128x128, BK=32, 8 warps (4x2), warp tile 32x64, m16n8k16.
// 3-stage cp.async ring, ONE barrier per iter, 2 CTAs/SM.
// Smem pitch 20 u32/row -> all frag LDS conflict-free.
// ---------------------------------------------------------------------------
#define GP     20                       // u32 pitch per row (16 used + 4 pad)
#define GS_A   (128 * GP)               // 2560 u32
#define GS_B   (128 * GP)               // 2560 u32
#define GSTG   (GS_A + GS_B)            // 5120 u32
#define G_SMEM (3 * GSTG * (int)sizeof(uint32_t))   // 61440 B

__device__ __forceinline__ void gemm_core_h(
    const __half* __restrict__ A, const __half* __restrict__ BT,
    void* __restrict__ C, bool half_out, int N, int K, int bx, int by,
    uint32_t* gsm)
{
    const int tid  = threadIdx.x;
    const int warp = tid >> 5;
    const int lane = tid & 31;
    const int g    = lane >> 2;
    const int t    = lane & 3;
    const int mbase = (warp >> 1) * 32;   // 0,32,64,96
    const int nbase = (warp & 1) * 64;    // 0,64

    const __half* Arow = A  + (size_t)(by * 128 + (tid >> 1)) * K + (tid & 1) * 16;
    const __half* Brow = BT + (size_t)(bx * 128 + (tid >> 1)) * K + (tid & 1) * 16;
    const int ab_off = (tid >> 1) * GP + (tid & 1) * 8;

    const int iters = K / 32;

    auto issue = [&](int it) {
        uint32_t* as = gsm + (it % 3) * GSTG;
        const __half* asrc = Arow + it * 32;
        cp_async16(&as[ab_off],     asrc);
        cp_async16(&as[ab_off + 4], asrc + 8);
        uint32_t* bs = as + GS_A;
        const __half* bsrc = Brow + it * 32;
        cp_async16(&bs[ab_off],     bsrc);
        cp_async16(&bs[ab_off + 4], bsrc + 8);
        asm volatile("cp.async.commit_group;\n" ::: "memory");
    };

    float acc[2][8][4];
    #pragma unroll
    for (int i = 0; i < 2; i++)
        #pragma unroll
        for (int j = 0; j < 8; j++)
            #pragma unroll
            for (int r = 0; r < 4; r++) acc[i][j][r] = 0.f;

    issue(0);
    if (iters > 1) issue(1);

    for (int it = 0; it < iters; it++) {
        if (it + 1 < iters)
            asm volatile("cp.async.wait_group 1;\n" ::: "memory");
        else
            asm volatile("cp.async.wait_group 0;\n" ::: "memory");
        __syncthreads();   // stage it landed AND all warps done reading it-1

        if (it + 2 < iters) issue(it + 2);   // overwrites buffer (it-1)%3

        const uint32_t* as = gsm + (it % 3) * GSTG;
        const uint32_t* bs = as + GS_A;

        #pragma unroll
        for (int kc = 0; kc < 2; kc++) {
            uint32_t af[2][4];
            #pragma unroll
            for (int mf = 0; mf < 2; mf++) {
                const int m0 = mbase + mf * 16 + g;
                af[mf][0] = as[(m0    ) * GP + 8 * kc + t];
                af[mf][1] = as[(m0 + 8) * GP + 8 * kc + t];
                af[mf][2] = as[(m0    ) * GP + 8 * kc + t + 4];
                af[mf][3] = as[(m0 + 8) * GP + 8 * kc + t + 4];
            }
            uint32_t bf[8][2];
            #pragma unroll
            for (int nf = 0; nf < 8; nf++) {
                const int n0 = nbase + nf * 8 + g;
                bf[nf][0] = bs[n0 * GP + 8 * kc + t];
                bf[nf][1] = bs[n0 * GP + 8 * kc + t + 4];
            }
            #pragma unroll
            for (int mf = 0; mf < 2; mf++)
                #pragma unroll
                for (int nf = 0; nf < 8; nf++)
                    mma_f16(acc[mf][nf], af[mf][0], af[mf][1], af[mf][2],
                            af[mf][3], bf[nf][0], bf[nf][1]);
        }
    }

    #pragma unroll
    for (int mf = 0; mf < 2; mf++) {
        const int row = by * 128 + mbase + mf * 16 + g;
        #pragma unroll
        for (int nf = 0; nf < 8; nf++) {
            const int col = bx * 128 + nbase + nf * 8 + 2 * t;
            if (half_out) {
                __half* Ch = (__half*)C;
                *(uint32_t*)(Ch + (size_t)row * N + col) =
                    pack_half2(acc[mf][nf][0], acc[mf][nf][1]);
                *(uint32_t*)(Ch + (size_t)(row + 8) * N + col) =
                    pack_half2(acc[mf][nf][2], acc[mf][nf][3]);
            } else {
                float* Cf = (float*)C;
                *(float2*)(Cf + (size_t)row * N + col) =
                    make_float2(acc[mf][nf][0], acc[mf][nf][1]);
                *(float2*)(Cf + (size_t)(row + 8) * N + col) =
                    make_float2(acc[mf][nf][2], acc[mf][nf][3]);
            }
        }
    }
}

// fused Q/K/V projection: grid (24, 32); bx<16 -> Q, <20 -> K, else -> V
__global__ __launch_bounds__(256, 2) void gemm_qkv(
    const __half* __restrict__ x,
    const __half* __restrict__ WqT, const __half* __restrict__ WkT,
    const __half* __restrict__ WvT,
    __half* __restrict__ Qp, __half* __restrict__ Kp, __half* __restrict__ Vp)
{
    extern __shared__ uint32_t gsm[];
    const int bx = blockIdx.x;
    if (bx < 16)      gemm_core_h(x, WqT, Qp, true, ND,   ND, bx,      blockIdx.y, gsm);
    else if (bx < 20) gemm_core_h(x, WkT, Kp, true, NDKV, ND, bx - 16, blockIdx.y, gsm);
    else              gemm_core_h(x, WvT, Vp, true, NDKV, ND, bx - 20, blockIdx.y, gsm);
}

__global__ __launch_bounds__(256, 2) void gemm_out(
    const __half* __restrict__ A, const __half* __restrict__ BT,
    float* __restrict__ C)
{
    extern __shared__ uint32_t gsm[];
    gemm_core_h(A, BT, C, false, ND, ND, blockIdx.x, blockIdx.y, gsm);
}

// ---------------------------------------------------------------------------
// fp16 MMA flash attention (unchanged from R8 — proven). Br=256, Bc=64.
// ---------------------------------------------------------------------------
#define FP       36
#define KBUF     (64 * FP)
#define FA_SMEM  (5 * KBUF * (int)sizeof(uint32_t))   // 46080 B
#define NTILES   (NT / 64)

__global__ __launch_bounds__(256) void flash_h(
    const __half* __restrict__ Q, const __half* __restrict__ K,
    const __half* __restrict__ V, __half* __restrict__ O)
{
    extern __shared__ uint32_t sm[];

    const int tid  = threadIdx.x;
    const int warp = tid >> 5;
    const int lane = tid & 31;
    const int g    = lane >> 2;
    const int tq   = lane & 3;
    const int bh   = blockIdx.y;
    const int b    = bh >> 5;
    const int h    = bh & 31;
    const int hkv  = h >> 2;
    const int q0   = blockIdx.x * 256;

    const int krow = tid >> 2;
    const int kq   = tid & 3;
    const int vt2  = tid & 31;
    const int vdb  = (tid >> 5) * 8;

    {
        const __half* s0 = K + (size_t)(b * NT + krow) * NDKV + hkv * NDH + kq * 16;
        cp_async16(&sm[krow * FP + kq * 8],     s0);
        cp_async16(&sm[krow * FP + kq * 8 + 4], s0 + 8);
        asm volatile("cp.async.commit_group;\n" ::: "memory");
        const __half* s1 = s0 + (size_t)64 * NDKV;
        cp_async16(&sm[KBUF + krow * FP + kq * 8],     s1);
        cp_async16(&sm[KBUF + krow * FP + kq * 8 + 4], s1 + 8);
        asm volatile("cp.async.commit_group;\n" ::: "memory");
    }
    uint4 v0, v1;
    {
        const __half* src = V + (size_t)(b * NT + 2 * vt2) * NDKV + hkv * NDH + vdb;
        v0 = *(const uint4*)(src);
        v1 = *(const uint4*)(src + NDKV);
    }
    const float QSC = 0.18033688011112042f;   // 0.125 * log2(e)
    const __half2 qsc2 = __float2half2_rn(QSC);
    uint32_t qa[2][4][4];
    {
        #pragma unroll
        for (int f = 0; f < 2; f++) {
            const size_t r0 = (size_t)(b * NT + q0 + warp * 32 + 16 * f + g);
            const uint32_t* p0 = (const uint32_t*)(Q + r0 * ND + h * NDH);
            const uint32_t* p1 = (const uint32_t*)(Q + (r0 + 8) * ND + h * NDH);
            #pragma unroll
            for (int kc = 0; kc < 4; kc++) {
                qa[f][kc][0] = p0[8 * kc + tq];
                qa[f][kc][1] = p1[8 * kc + tq];
                qa[f][kc][2] = p0[8 * kc + tq + 4];
                qa[f][kc][3] = p1[8 * kc + tq + 4];
                #pragma unroll
                for (int r = 0; r < 4; r++) {
                    __half2 hv = __hmul2(*(const __half2*)&qa[f][kc][r], qsc2);
                    qa[f][kc][r] = *(const uint32_t*)&hv;
                }
            }
        }
    }
    {
        uint32_t* dst = sm + 3 * KBUF;
        const __half* h0 = (const __half*)&v0;
        const __half* h1 = (const __half*)&v1;
        #pragma unroll
        for (int i = 0; i < 8; i++) {
            __half2 p = __halves2half2(h0[i], h1[i]);
            dst[(vdb + i) * FP + vt2] = *(const uint32_t*)&p;
        }
    }
    {
        const __half* src = V + (size_t)(b * NT + 64 + 2 * vt2) * NDKV + hkv * NDH + vdb;
        v0 = *(const uint4*)(src);
        v1 = *(const uint4*)(src + NDKV);
    }
    __syncthreads();

    float mrow[2][2], lrow[2][2];
    #pragma unroll
    for (int f = 0; f < 2; f++) { mrow[f][0] = mrow[f][1] = -1e30f;
                                  lrow[f][0] = lrow[f][1] = 0.f; }
    float acc_o[2][8][4];
    #pragma unroll
    for (int f = 0; f < 2; f++)
        #pragma unroll
        for (int j = 0; j < 8; j++)
            #pragma unroll
            for (int r = 0; r < 4; r++) acc_o[f][j][r] = 0.f;

    const unsigned fm = 0xffffffffu;

    for (int kb = 0; kb < NTILES; kb++) {
        const int vb   = kb & 1;
        const bool pre1 = kb + 1 < NTILES;
        const bool pre2 = kb + 2 < NTILES;

        if (pre1) asm volatile("cp.async.wait_group 1;\n" ::: "memory");
        else      asm volatile("cp.async.wait_group 0;\n" ::: "memory");
        __syncthreads();

        if (pre2) {
            uint32_t* kdst = sm + ((kb + 2) % 3) * KBUF;
            const __half* src = K + (size_t)(b * NT + (kb + 2) * 64 + krow) * NDKV
                                + hkv * NDH + kq * 16;
            cp_async16(&kdst[krow * FP + kq * 8],     src);
            cp_async16(&kdst[krow * FP + kq * 8 + 4], src + 8);
            asm volatile("cp.async.commit_group;\n" ::: "memory");
        }

        float s[2][8][4];
        #pragma unroll
        for (int f = 0; f < 2; f++)
            #pragma unroll
            for (int j = 0; j < 8; j++)
                #pragma unroll
                for (int r = 0; r < 4; r++) s[f][j][r] = 0.f;
        {
            const uint32_t* kp = sm + (kb % 3) * KBUF;
            #pragma unroll
            for (int kc = 0; kc < 4; kc++)
                #pragma unroll
                for (int j = 0; j < 8; j++) {
                    const uint32_t b0 = kp[(8 * j + g) * FP + 8 * kc + tq];
                    const uint32_t b1 = kp[(8 * j + g) * FP + 8 * kc + tq + 4];
                    mma_f16(s[0][j], qa[0][kc][0], qa[0][kc][1], qa[0][kc][2],
                            qa[0][kc][3], b0, b1);
                    mma_f16(s[1][j], qa[1][kc][0], qa[1][kc][1], qa[1][kc][2],
                            qa[1][kc][3], b0, b1);
                }
        }

        if (pre1) {
            uint32_t* dst = sm + (3 + (vb ^ 1)) * KBUF;
            const __half* h0 = (const __half*)&v0;
            const __half* h1 = (const __half*)&v1;
            #pragma unroll
            for (int i = 0; i < 8; i++) {
                __half2 p = __halves2half2(h0[i], h1[i]);
                dst[(vdb + i) * FP + vt2] = *(const uint32_t*)&p;
            }
        }
        if (pre2) {
            const __half* src = V + (size_t)(b * NT + (kb + 2) * 64 + 2 * vt2) * NDKV
                                + hkv * NDH + vdb;
            v0 = *(const uint4*)(src);
            v1 = *(const uint4*)(src + NDKV);
        }

        #pragma unroll
        for (int f = 0; f < 2; f++) {
            float mt0 = -1e30f, mt1 = -1e30f;
            #pragma unroll
            for (int j = 0; j < 8; j++) {
                mt0 = fmaxf(mt0, fmaxf(s[f][j][0], s[f][j][1]));
                mt1 = fmaxf(mt1, fmaxf(s[f][j][2], s[f][j][3]));
            }
            mt0 = fmaxf(mt0, __shfl_xor_sync(fm, mt0, 1));
            mt0 = fmaxf(mt0, __shfl_xor_sync(fm, mt0, 2));
            mt1 = fmaxf(mt1, __shfl_xor_sync(fm, mt1, 1));
            mt1 = fmaxf(mt1, __shfl_xor_sync(fm, mt1, 2));
            const float mn0 = fmaxf(mrow[f][0], mt0);
            const float mn1 = fmaxf(mrow[f][1], mt1);
            const float al0 = exp2f(mrow[f][0] - mn0);
            const float al1 = exp2f(mrow[f][1] - mn1);
            mrow[f][0] = mn0; mrow[f][1] = mn1;
            float rs0 = 0.f, rs1 = 0.f;
            #pragma unroll
            for (int j = 0; j < 8; j++) {
                s[f][j][0] = exp2f(s[f][j][0] - mn0); rs0 += s[f][j][0];
                s[f][j][1] = exp2f(s[f][j][1] - mn0); rs0 += s[f][j][1];
                s[f][j][2] = exp2f(s[f][j][2] - mn1); rs1 += s[f][j][2];
                s[f][j][3] = exp2f(s[f][j][3] - mn1); rs1 += s[f][j][3];
            }
            rs0 += __shfl_xor_sync(fm, rs0, 1);
            rs0 += __shfl_xor_sync(fm, rs0, 2);
            rs1 += __shfl_xor_sync(fm, rs1, 1);
            rs1 += __shfl_xor_sync(fm, rs1, 2);
            lrow[f][0] = lrow[f][0] * al0 + rs0;
            lrow[f][1] = lrow[f][1] * al1 + rs1;
            #pragma unroll
            for (int j = 0; j < 8; j++) {
                acc_o[f][j][0] *= al0; acc_o[f][j][1] *= al0;
                acc_o[f][j][2] *= al1; acc_o[f][j][3] *= al1;
            }
        }

        {
            const uint32_t* vt = sm + (3 + vb) * KBUF;
            #pragma unroll
            for (int kc = 0; kc < 4; kc++) {
                uint32_t pa[2][4];
                #pragma unroll
                for (int f = 0; f < 2; f++) {
                    pa[f][0] = pack_half2(s[f][2 * kc][0],     s[f][2 * kc][1]);
                    pa[f][1] = pack_half2(s[f][2 * kc][2],     s[f][2 * kc][3]);
                    pa[f][2] = pack_half2(s[f][2 * kc + 1][0], s[f][2 * kc + 1][1]);
                    pa[f][3] = pack_half2(s[f][2 * kc + 1][2], s[f][2 * kc + 1][3]);
                }
                #pragma unroll
                for (int jd = 0; jd < 8; jd++) {
                    const uint32_t b0 = vt[(8 * jd + g) * FP + 8 * kc + tq];
                    const uint32_t b1 = vt[(8 * jd + g) * FP + 8 * kc + tq + 4];
                    mma_f16(acc_o[0][jd], pa[0][0], pa[0][1], pa[0][2], pa[0][3], b0, b1);
                    mma_f16(acc_o[1][jd], pa[1][0], pa[1][1], pa[1][2], pa[1][3], b0, b1);
                }
            }
        }
    }

    #pragma unroll
    for (int f = 0; f < 2; f++) {
        const float inv0 = 1.0f / lrow[f][0];
        const float inv1 = 1.0f / lrow[f][1];
        const size_t r0 = (size_t)(b * NT + q0 + warp * 32 + 16 * f + g);
        __half* o0 = O + r0 * ND + h * NDH;
        __half* o1 = o0 + (size_t)8 * ND;
        #pragma unroll
        for (int jd = 0; jd < 8; jd++) {
            *(uint32_t*)(o0 + 8 * jd + 2 * tq) =
                pack_half2(acc_o[f][jd][0] * inv0, acc_o[f][jd][1] * inv0);
            *(uint32_t*)(o1 + 8 * jd + 2 * tq) =
                pack_half2(acc_o[f][jd][2] * inv1, acc_o[f][jd][3] * inv1);
        }
    }
}

// ---------------------------------------------------------------------------
extern "C" void kernel_launch(void* const* d_in, const int* in_sizes, int n_in,
                              void* d_out, int out_size)
{
    const float* x  = (const float*)d_in[0];
    const float* Wq = (const float*)d_in[1];
    const float* Wk = (const float*)d_in[2];
    const float* Wv = (const float*)d_in[3];
    const float* Wo = (const float*)d_in[4];
    float* out = (float*)d_out;

    __half *Qh, *Kh, *Vh, *Ah, *Xh, *WqT, *WkT, *WvT, *WoT;
    cudaGetSymbolAddress((void**)&Qh,  g_Qh);
    cudaGetSymbolAddress((void**)&Kh,  g_Kh);
    cudaGetSymbolAddress((void**)&Vh,  g_Vh);
    cudaGetSymbolAddress((void**)&Ah,  g_Ah);
    cudaGetSymbolAddress((void**)&Xh,  g_Xh);
    cudaGetSymbolAddress((void**)&WqT, g_WqT);
    cudaGetSymbolAddress((void**)&WkT, g_WkT);
    cudaGetSymbolAddress((void**)&WvT, g_WvT);
    cudaGetSymbolAddress((void**)&WoT, g_WoT);

    cudaFuncSetAttribute(flash_h,
                         cudaFuncAttributeMaxDynamicSharedMemorySize, FA_SMEM);
    cudaFuncSetAttribute(gemm_qkv,
                         cudaFuncAttributeMaxDynamicSharedMemorySize, G_SMEM);
    cudaFuncSetAttribute(gemm_out,
                         cudaFuncAttributeMaxDynamicSharedMemorySize, G_SMEM);

    const int nX = NTOK * ND / 4;
    cvt_half<<<(nX + 255) / 256, 256>>>(x, Xh, nX);
    transpose4<<<dim3(ND / 32, ND / 32, 4), 256>>>(Wq, Wk, Wv, Wo,
                                                   WqT, WkT, WvT, WoT);

    gemm_qkv<<<dim3(24, 32), 256, G_SMEM>>>(Xh, WqT, WkT, WvT, Qh, Kh, Vh);
    flash_h<<<dim3(NT / 256, NB * NHQ), 256, FA_SMEM>>>(Qh, Kh, Vh, Ah);
    gemm_out<<<dim3(16, 32), 256, G_SMEM>>>(Ah, WoT, out);
}